// round 1
// baseline (speedup 1.0000x reference)
#include <cuda_runtime.h>
#include <cstdint>

typedef unsigned long long ull;

#define NMAX    1000000
#define BGRAPH  2000

// ---------------- scratch (device globals: allocation-free rule) --------------
__device__ __align__(16) float g_x0[(size_t)NMAX * 64];    // 256 MB
__device__ __align__(16) float g_h1[(size_t)NMAX * 64];    // 256 MB
__device__ __align__(16) float g_v [(size_t)NMAX * 128];   // 512 MB
__device__ __align__(16) float g_xm1[BGRAPH * 64];
__device__ __align__(16) float g_xm2[BGRAPH * 128];
__device__ float g_fsum[128];
__device__ float g_fsq [128];
__device__ __align__(16) float g_scale[128];
__device__ __align__(16) float g_shift[128];

// ---------------- f32x2 helpers (Blackwell packed fp32) -----------------------
__device__ __forceinline__ void ffma2(ull &acc, ull a, ull b) {
    asm("fma.rn.f32x2 %0, %1, %2, %0;" : "+l"(acc) : "l"(a), "l"(b));
}
__device__ __forceinline__ ull pack2(float x) {
    ull r; unsigned u = __float_as_uint(x);
    asm("mov.b64 %0, {%1, %1};" : "=l"(r) : "r"(u));
    return r;
}
__device__ __forceinline__ float2 unpk(ull v) {
    unsigned lo, hi;
    asm("mov.b64 {%0, %1}, %2;" : "=r"(lo), "=r"(hi) : "l"(v));
    return make_float2(__uint_as_float(lo), __uint_as_float(hi));
}

__device__ __forceinline__ void mma_step(ull (*acc)[4], const float *av,
                                         ull w0, ull w1, ull w2, ull w3) {
#pragma unroll
    for (int r = 0; r < 8; r++) {
        ull ar = pack2(av[r]);
        ffma2(acc[r][0], ar, w0);
        ffma2(acc[r][1], ar, w1);
        ffma2(acc[r][2], ar, w2);
        ffma2(acc[r][3], ar, w3);
    }
}

// ---------------- K0: zero BN accumulators ------------------------------------
__global__ void k0_zero() {
    int t = threadIdx.x;
    if (t < 128) { g_fsum[t] = 0.f; g_fsq[t] = 0.f; }
}

// ---------------- K1: x0 = relu(pack(pp) @ W0 + b0) ---------------------------
// [N,16] @ [16,64], BM=256, thread tile 8x8 (split-half cols), 256 threads.
__global__ __launch_bounds__(256) void k1_x0(
    const float* __restrict__ pp, const float* __restrict__ W0,
    const float* __restrict__ b0, int N)
{
    __shared__ __align__(16) float As[16][260];   // transposed [k][row]
    __shared__ __align__(16) float Ws[16 * 64];
    int tid = threadIdx.x;
    int n0  = blockIdx.x * 256;

    for (int i = tid; i < 16 * 64; i += 256) Ws[i] = W0[i];

    const float2* pp2 = (const float2*)pp;
    int n = n0 + tid;
#pragma unroll
    for (int f = 0; f < 8; f++) {
        float2 v = (n < N) ? pp2[(size_t)f * N + n] : make_float2(0.f, 0.f);
        As[2*f  ][tid] = v.x;
        As[2*f+1][tid] = v.y;
    }
    __syncthreads();

    int rg = tid >> 3, cg = tid & 7;   // 32 row-groups x 8 col-groups
    ull acc[8][4];
#pragma unroll
    for (int r = 0; r < 8; r++)
#pragma unroll
        for (int c = 0; c < 4; c++) acc[r][c] = 0ull;

    const ull* Wsu = (const ull*)Ws;
#pragma unroll
    for (int k = 0; k < 16; k++) {
        float4 a0 = *(const float4*)&As[k][rg*8];
        float4 a1 = *(const float4*)&As[k][rg*8 + 4];
        ull w0 = Wsu[k*32 + cg*2];
        ull w1 = Wsu[k*32 + cg*2 + 1];
        ull w2 = Wsu[k*32 + 16 + cg*2];
        ull w3 = Wsu[k*32 + 16 + cg*2 + 1];
        float av[8] = {a0.x, a0.y, a0.z, a0.w, a1.x, a1.y, a1.z, a1.w};
        mma_step(acc, av, w0, w1, w2, w3);
    }

    float4 bl = *(const float4*)&b0[cg*4];
    float4 bh = *(const float4*)&b0[32 + cg*4];
#pragma unroll
    for (int r = 0; r < 8; r++) {
        int row = n0 + rg*8 + r;
        if (row < N) {
            float2 p0 = unpk(acc[r][0]), p1 = unpk(acc[r][1]);
            float2 p2 = unpk(acc[r][2]), p3 = unpk(acc[r][3]);
            float4 o0 = make_float4(fmaxf(p0.x + bl.x, 0.f), fmaxf(p0.y + bl.y, 0.f),
                                    fmaxf(p1.x + bl.z, 0.f), fmaxf(p1.y + bl.w, 0.f));
            float4 o1 = make_float4(fmaxf(p2.x + bh.x, 0.f), fmaxf(p2.y + bh.y, 0.f),
                                    fmaxf(p3.x + bh.z, 0.f), fmaxf(p3.y + bh.w, 0.f));
            *(float4*)&g_x0[(size_t)row*64 + cg*4]      = o0;
            *(float4*)&g_x0[(size_t)row*64 + 32 + cg*4] = o1;
        }
    }
}

// ---------------- K2/K4: segment mean + projection ----------------------------
__device__ __forceinline__ int lbound(const int* __restrict__ a, int n, int v) {
    int lo = 0, hi = n;
    while (lo < hi) { int m = (lo + hi) >> 1; if (__ldg(a + m) < v) lo = m + 1; else hi = m; }
    return lo;
}

template<int DOUT>
__device__ void seg_mean_proj(const float* __restrict__ h, const int* __restrict__ batch,
                              const float* __restrict__ lw, float* __restrict__ xm, int N)
{
    __shared__ int   bnd[2];
    __shared__ float psum[4][64];
    __shared__ float smean[64];
    int tid = threadIdx.x;
    int b   = blockIdx.x;
    if (tid == 0) { bnd[0] = lbound(batch, N, b); bnd[1] = lbound(batch, N, b + 1); }
    __syncthreads();
    int lo = bnd[0], hi = bnd[1];
    int j = tid & 63, sl = tid >> 6;
    float acc = 0.f;
#pragma unroll 4
    for (int r = lo + sl; r < hi; r += 4) acc += h[(size_t)r * 64 + j];
    psum[sl][j] = acc;
    __syncthreads();
    if (tid < 64) {
        float s = psum[0][j] + psum[1][j] + psum[2][j] + psum[3][j];
        int cnt = hi - lo;
        float c = (float)(cnt > 0 ? cnt : 1);
        smean[j] = s / c;
    }
    __syncthreads();
    if (tid < DOUT) {
        float s = 0.f;
#pragma unroll
        for (int k = 0; k < 64; k++) s += smean[k] * lw[k * DOUT + tid];
        xm[b * DOUT + tid] = s;
    }
}

__global__ __launch_bounds__(256) void k2_xm1(const int* __restrict__ batch,
                                              const float* __restrict__ l1w, int N)
{ seg_mean_proj<64>(g_x0, batch, l1w, g_xm1, N); }

__global__ __launch_bounds__(256) void k4_xm2(const int* __restrict__ batch,
                                              const float* __restrict__ l2w, int N)
{ seg_mean_proj<128>(g_h1, batch, l2w, g_xm2, N); }

// ---------------- K3: h1 = relu(x0 @ g1_w + g1_b - xm1[batch]) -----------------
// [N,64] @ [64,64], BM=256, K chunked by 16, 256 threads, thread tile 8x8.
__global__ __launch_bounds__(256) void k3_h1(
    const float* __restrict__ gw, const float* __restrict__ gb,
    const int* __restrict__ batch, int N)
{
    __shared__ __align__(16) float As[16][260];
    __shared__ __align__(16) float Ws[64 * 64];
    int tid = threadIdx.x;
    int n0  = blockIdx.x * 256;
    for (int i = tid; i < 64 * 64; i += 256) Ws[i] = gw[i];

    int rg = tid >> 3, cg = tid & 7;
    ull acc[8][4];
#pragma unroll
    for (int r = 0; r < 8; r++)
#pragma unroll
        for (int c = 0; c < 4; c++) acc[r][c] = 0ull;

    const ull* Wsu = (const ull*)Ws;
    int kk4 = tid & 3, nn = tid >> 2;   // loader mapping

    for (int kc = 0; kc < 4; kc++) {
        __syncthreads();
#pragma unroll
        for (int p = 0; p < 4; p++) {
            int nrow = n0 + nn + p * 64;
            float4 v = (nrow < N)
                ? *(const float4*)&g_x0[(size_t)nrow * 64 + kc * 16 + kk4 * 4]
                : make_float4(0.f, 0.f, 0.f, 0.f);
            As[kk4*4 + 0][nn + p*64] = v.x;
            As[kk4*4 + 1][nn + p*64] = v.y;
            As[kk4*4 + 2][nn + p*64] = v.z;
            As[kk4*4 + 3][nn + p*64] = v.w;
        }
        __syncthreads();
#pragma unroll
        for (int k = 0; k < 16; k++) {
            float4 a0 = *(const float4*)&As[k][rg*8];
            float4 a1 = *(const float4*)&As[k][rg*8 + 4];
            int kg = kc * 16 + k;
            ull w0 = Wsu[kg*32 + cg*2];
            ull w1 = Wsu[kg*32 + cg*2 + 1];
            ull w2 = Wsu[kg*32 + 16 + cg*2];
            ull w3 = Wsu[kg*32 + 16 + cg*2 + 1];
            float av[8] = {a0.x, a0.y, a0.z, a0.w, a1.x, a1.y, a1.z, a1.w};
            mma_step(acc, av, w0, w1, w2, w3);
        }
    }

    float4 bl = *(const float4*)&gb[cg*4];
    float4 bh = *(const float4*)&gb[32 + cg*4];
#pragma unroll
    for (int r = 0; r < 8; r++) {
        int row = n0 + rg*8 + r;
        if (row < N) {
            int b = batch[row];
            float4 xl = *(const float4*)&g_xm1[b*64 + cg*4];
            float4 xh = *(const float4*)&g_xm1[b*64 + 32 + cg*4];
            float2 p0 = unpk(acc[r][0]), p1 = unpk(acc[r][1]);
            float2 p2 = unpk(acc[r][2]), p3 = unpk(acc[r][3]);
            float4 o0 = make_float4(fmaxf(p0.x + bl.x - xl.x, 0.f),
                                    fmaxf(p0.y + bl.y - xl.y, 0.f),
                                    fmaxf(p1.x + bl.z - xl.z, 0.f),
                                    fmaxf(p1.y + bl.w - xl.w, 0.f));
            float4 o1 = make_float4(fmaxf(p2.x + bh.x - xh.x, 0.f),
                                    fmaxf(p2.y + bh.y - xh.y, 0.f),
                                    fmaxf(p3.x + bh.z - xh.z, 0.f),
                                    fmaxf(p3.y + bh.w - xh.w, 0.f));
            *(float4*)&g_h1[(size_t)row*64 + cg*4]      = o0;
            *(float4*)&g_h1[(size_t)row*64 + 32 + cg*4] = o1;
        }
    }
}

// ---------------- K5: v = relu(h1 @ g2_w + g2_b - xm2[batch]); BN stats -------
// [N,64] @ [64,128], BM=128, BN=128, 256 threads, thread tile 8x8.
__global__ __launch_bounds__(256) void k5_v(
    const float* __restrict__ gw, const float* __restrict__ gb,
    const int* __restrict__ batch, int N)
{
    __shared__ __align__(16) float As[16][132];   // also reused as reduction buf
    __shared__ __align__(16) float Ws[64 * 128];
    int tid = threadIdx.x;
    int n0  = blockIdx.x * 128;
    for (int i = tid; i < 64 * 128; i += 256) Ws[i] = gw[i];

    int rg = tid >> 4, cg = tid & 15;   // 16 rg x 16 cg
    ull acc[8][4];
#pragma unroll
    for (int r = 0; r < 8; r++)
#pragma unroll
        for (int c = 0; c < 4; c++) acc[r][c] = 0ull;

    const ull* Wsu = (const ull*)Ws;
    int kk4 = tid & 3, nn = tid >> 2;   // nn 0..63

    for (int kc = 0; kc < 4; kc++) {
        __syncthreads();
#pragma unroll
        for (int p = 0; p < 2; p++) {
            int nrow = n0 + nn + p * 64;
            float4 v = (nrow < N)
                ? *(const float4*)&g_h1[(size_t)nrow * 64 + kc * 16 + kk4 * 4]
                : make_float4(0.f, 0.f, 0.f, 0.f);
            As[kk4*4 + 0][nn + p*64] = v.x;
            As[kk4*4 + 1][nn + p*64] = v.y;
            As[kk4*4 + 2][nn + p*64] = v.z;
            As[kk4*4 + 3][nn + p*64] = v.w;
        }
        __syncthreads();
#pragma unroll
        for (int k = 0; k < 16; k++) {
            float4 a0 = *(const float4*)&As[k][rg*8];
            float4 a1 = *(const float4*)&As[k][rg*8 + 4];
            int kg = kc * 16 + k;
            ull w0 = Wsu[kg*64 + cg*2];
            ull w1 = Wsu[kg*64 + cg*2 + 1];
            ull w2 = Wsu[kg*64 + 32 + cg*2];
            ull w3 = Wsu[kg*64 + 32 + cg*2 + 1];
            float av[8] = {a0.x, a0.y, a0.z, a0.w, a1.x, a1.y, a1.z, a1.w};
            mma_step(acc, av, w0, w1, w2, w3);
        }
    }

    float4 bl = *(const float4*)&gb[cg*4];
    float4 bh = *(const float4*)&gb[64 + cg*4];
    float cs[8], cq[8];
#pragma unroll
    for (int i = 0; i < 8; i++) { cs[i] = 0.f; cq[i] = 0.f; }

#pragma unroll
    for (int r = 0; r < 8; r++) {
        int row = n0 + rg*8 + r;
        if (row < N) {
            int b = batch[row];
            float4 xl = *(const float4*)&g_xm2[b*128 + cg*4];
            float4 xh = *(const float4*)&g_xm2[b*128 + 64 + cg*4];
            float2 p0 = unpk(acc[r][0]), p1 = unpk(acc[r][1]);
            float2 p2 = unpk(acc[r][2]), p3 = unpk(acc[r][3]);
            float o[8];
            o[0] = fmaxf(p0.x + bl.x - xl.x, 0.f);
            o[1] = fmaxf(p0.y + bl.y - xl.y, 0.f);
            o[2] = fmaxf(p1.x + bl.z - xl.z, 0.f);
            o[3] = fmaxf(p1.y + bl.w - xl.w, 0.f);
            o[4] = fmaxf(p2.x + bh.x - xh.x, 0.f);
            o[5] = fmaxf(p2.y + bh.y - xh.y, 0.f);
            o[6] = fmaxf(p3.x + bh.z - xh.z, 0.f);
            o[7] = fmaxf(p3.y + bh.w - xh.w, 0.f);
            *(float4*)&g_v[(size_t)row*128 + cg*4]      = make_float4(o[0], o[1], o[2], o[3]);
            *(float4*)&g_v[(size_t)row*128 + 64 + cg*4] = make_float4(o[4], o[5], o[6], o[7]);
#pragma unroll
            for (int i = 0; i < 8; i++) { cs[i] += o[i]; cq[i] += o[i] * o[i]; }
        }
    }

    // reduce stats: shfl over rg-pair within warp, then smem over 8 warps
#pragma unroll
    for (int i = 0; i < 8; i++) {
        cs[i] += __shfl_xor_sync(0xffffffffu, cs[i], 16);
        cq[i] += __shfl_xor_sync(0xffffffffu, cq[i], 16);
    }
    __syncthreads();                    // done with As as GEMM tile
    float* red = &As[0][0];             // [8 warps][16 cg][16]
    int lane = tid & 31, w = tid >> 5;
    if (lane < 16) {
#pragma unroll
        for (int i = 0; i < 8; i++) {
            red[w*256 + lane*16 + i]     = cs[i];
            red[w*256 + lane*16 + 8 + i] = cq[i];
        }
    }
    __syncthreads();
    if (tid < 128) {
        int c   = tid;
        int cg2 = (c < 64) ? (c >> 2) : ((c - 64) >> 2);
        int ii  = (c < 64) ? (c & 3)  : 4 + (c & 3);
        float s = 0.f, q = 0.f;
#pragma unroll
        for (int w2 = 0; w2 < 8; w2++) {
            s += red[w2*256 + cg2*16 + ii];
            q += red[w2*256 + cg2*16 + 8 + ii];
        }
        atomicAdd(&g_fsum[c], s);
        atomicAdd(&g_fsq[c],  q);
    }
}

// ---------------- K5b: fold BN into scale/shift -------------------------------
__global__ void k5b_stats(const float* __restrict__ gamma,
                          const float* __restrict__ beta, float invN)
{
    int t = threadIdx.x;
    if (t < 128) {
        float m   = g_fsum[t] * invN;
        float var = g_fsq[t] * invN - m * m;
        float rs  = rsqrtf(var + 1e-5f);
        float sc  = gamma[t] * rs;
        g_scale[t] = sc;
        g_shift[t] = beta[t] - m * sc;
    }
}

// ---------------- K6: out = x + v*scale + shift -------------------------------
__global__ __launch_bounds__(256) void k6_out(const float* __restrict__ x,
                                              float* __restrict__ out, int n4)
{
    int i = blockIdx.x * 256 + threadIdx.x;
    if (i < n4) {
        float4 xv = ((const float4*)x)[i];
        float4 vv = ((const float4*)g_v)[i];
        int f = i & 31;                      // 32 float4 per 128-wide row
        float4 sc = ((const float4*)g_scale)[f];
        float4 sh = ((const float4*)g_shift)[f];
        float4 o;
        o.x = xv.x + vv.x * sc.x + sh.x;
        o.y = xv.y + vv.y * sc.y + sh.y;
        o.z = xv.z + vv.z * sc.z + sh.z;
        o.w = xv.w + vv.w * sc.w + sh.w;
        ((float4*)out)[i] = o;
    }
}

// ---------------- launch -------------------------------------------------------
extern "C" void kernel_launch(void* const* d_in, const int* in_sizes, int n_in,
                              void* d_out, int out_size)
{
    const float* x    = (const float*)d_in[0];
    const float* pp   = (const float*)d_in[1];
    const int*   batch= (const int*)  d_in[2];
    const float* W0   = (const float*)d_in[3];
    const float* b0   = (const float*)d_in[4];
    const float* g1w  = (const float*)d_in[5];
    const float* g1b  = (const float*)d_in[6];
    const float* l1w  = (const float*)d_in[7];
    const float* g2w  = (const float*)d_in[8];
    const float* g2b  = (const float*)d_in[9];
    const float* l2w  = (const float*)d_in[10];
    const float* bng  = (const float*)d_in[11];
    const float* bnb  = (const float*)d_in[12];
    float* out = (float*)d_out;

    int N = in_sizes[2];                       // number of nodes
    int nb256 = (N + 255) / 256;
    int nb128 = (N + 127) / 128;
    int n4    = (N * 128) / 4;

    k0_zero<<<1, 128>>>();
    k1_x0 <<<nb256, 256>>>(pp, W0, b0, N);
    k2_xm1<<<BGRAPH, 256>>>(batch, l1w, N);
    k3_h1 <<<nb256, 256>>>(g1w, g1b, batch, N);
    k4_xm2<<<BGRAPH, 256>>>(batch, l2w, N);
    k5_v  <<<nb128, 256>>>(g2w, g2b, batch, N);
    k5b_stats<<<1, 128>>>(bng, bnb, 1.0f / (float)N);
    k6_out<<<(n4 + 255) / 256, 256>>>(x, out, n4);
}

// round 5
// speedup vs baseline: 1.0902x; 1.0902x over previous
#include <cuda_runtime.h>
#include <cuda_fp16.h>
#include <cstdint>

typedef unsigned long long ull;

#define NMAX 1000000
#define BG   2000

// ---------------- scratch (device globals: allocation-free rule) --------------
__device__ __align__(16) float  g_x0[(size_t)NMAX * 64];    // 256 MB
__device__ __align__(16) float  g_h1[(size_t)NMAX * 64];    // 256 MB
__device__ __align__(16) __half g_vh[(size_t)NMAX * 128];   // 256 MB (fp16 v)
__device__ __align__(16) float  g_seg1[BG * 64];            // seg sums of x0
__device__ __align__(16) float  g_seg2[BG * 64];            // seg sums of h1
__device__ __align__(16) float  g_xm1[BG * 64];
__device__ __align__(16) float  g_xm2[BG * 128];
__device__ float g_inv[BG];
__device__ float g_fsum[128];
__device__ float g_fsq [128];
__device__ __align__(16) float g_scale[128];
__device__ __align__(16) float g_shift[128];

// ---------------- f32x2 helpers (Blackwell packed fp32) -----------------------
__device__ __forceinline__ void ffma2(ull &acc, ull a, ull b) {
    asm("fma.rn.f32x2 %0, %1, %2, %0;" : "+l"(acc) : "l"(a), "l"(b));
}
__device__ __forceinline__ ull pack2(float x) {
    ull r; unsigned u = __float_as_uint(x);
    asm("mov.b64 %0, {%1, %1};" : "=l"(r) : "r"(u));
    return r;
}
__device__ __forceinline__ float2 unpk(ull v) {
    unsigned lo, hi;
    asm("mov.b64 {%0, %1}, %2;" : "=r"(lo), "=r"(hi) : "l"(v));
    return make_float2(__uint_as_float(lo), __uint_as_float(hi));
}

__device__ __forceinline__ int lbound(const int* __restrict__ a, int n, int v) {
    int lo = 0, hi = n;
    while (lo < hi) { int m = (lo + hi) >> 1; if (__ldg(a + m) < v) lo = m + 1; else hi = m; }
    return lo;
}

// ---------------- K0: zero accumulators ---------------------------------------
__global__ void k0_zero() {
    int i = blockIdx.x * 256 + threadIdx.x;
    if (i < BG * 64) g_seg1[i] = 0.f;
    int j = i - BG * 64;
    if (j >= 0 && j < BG * 64) g_seg2[j] = 0.f;
    int k = i - 2 * BG * 64;
    if (k >= 0 && k < 128) { g_fsum[k] = 0.f; g_fsq[k] = 0.f; }
}

// ---------------- KC: inverse counts -------------------------------------------
__global__ void kc_inv(const int* __restrict__ batch, int N) {
    int b = blockIdx.x * 256 + threadIdx.x;
    if (b < BG) {
        int lo = lbound(batch, N, b), hi = lbound(batch, N, b + 1);
        int c = hi - lo;
        g_inv[b] = 1.f / (float)(c > 0 ? c : 1);
    }
}

// ---------------- K1: x0 = relu(pack(pp) @ W0 + b0); fused seg-sum -------------
// BM=128, 256 threads, thread tile 8 rows x 4 cols (rg=tid>>4, cg=tid&15).
__global__ __launch_bounds__(256) void k1_x0(
    const float* __restrict__ pp, const float* __restrict__ W0,
    const float* __restrict__ b0, const int* __restrict__ batch, int N)
{
    __shared__ __align__(16) float As[16][132];     // transposed [k][row]; 132*4 % 16 == 0
    __shared__ __align__(16) float Ws[16 * 64];
    __shared__ __align__(16) float segbuf[16][64];
    __shared__ int sb[128];
    int tid = threadIdx.x;
    int n0  = blockIdx.x * 128;

    for (int i = tid; i < 16 * 64; i += 256) Ws[i] = W0[i];
    for (int i = tid; i < 16 * 64; i += 256) ((float*)segbuf)[i] = 0.f;
    if (tid < 128) { int r = n0 + tid; sb[tid] = (r < N) ? batch[r] : batch[N - 1]; }

    const float2* pp2 = (const float2*)pp;
    {
        int n  = tid & 127;
        int fb = tid >> 7;
        int gn = n0 + n;
#pragma unroll
        for (int p = 0; p < 4; p++) {
            int f = fb + 2 * p;
            float2 v = (gn < N) ? pp2[(size_t)f * N + gn] : make_float2(0.f, 0.f);
            As[2*f    ][n] = v.x;
            As[2*f + 1][n] = v.y;
        }
    }
    __syncthreads();

    int rg = tid >> 4, cg = tid & 15;
    ull acc[8][2];
#pragma unroll
    for (int r = 0; r < 8; r++) { acc[r][0] = 0ull; acc[r][1] = 0ull; }

    const ull* Wsu = (const ull*)Ws;
#pragma unroll
    for (int k = 0; k < 16; k++) {
        float4 a0 = *(const float4*)&As[k][rg*8];
        float4 a1 = *(const float4*)&As[k][rg*8 + 4];
        ull w0 = Wsu[k*32 + cg*2];
        ull w1 = Wsu[k*32 + cg*2 + 1];
        float av[8] = {a0.x, a0.y, a0.z, a0.w, a1.x, a1.y, a1.z, a1.w};
#pragma unroll
        for (int r = 0; r < 8; r++) {
            ull ar = pack2(av[r]);
            ffma2(acc[r][0], ar, w0);
            ffma2(acc[r][1], ar, w1);
        }
    }

    int sb0 = sb[0];
    int nseg = sb[127] - sb0 + 1;
    bool spill = nseg > 16;

    float4 bias = *(const float4*)&b0[cg*4];
    int cur = -1;
    float rs0 = 0.f, rs1 = 0.f, rs2 = 0.f, rs3 = 0.f;
#pragma unroll
    for (int r = 0; r < 8; r++) {
        int lr  = rg*8 + r;
        int row = n0 + lr;
        if (row < N) {
            float2 p0 = unpk(acc[r][0]), p1 = unpk(acc[r][1]);
            float o0 = fmaxf(p0.x + bias.x, 0.f);
            float o1 = fmaxf(p0.y + bias.y, 0.f);
            float o2 = fmaxf(p1.x + bias.z, 0.f);
            float o3 = fmaxf(p1.y + bias.w, 0.f);
            *(float4*)&g_x0[(size_t)row*64 + cg*4] = make_float4(o0, o1, o2, o3);
            int b = sb[lr];
            if (b != cur) {
                if (cur >= 0) {
                    float* dst = spill ? &g_seg1[cur*64 + cg*4] : &segbuf[cur - sb0][cg*4];
                    atomicAdd(dst + 0, rs0); atomicAdd(dst + 1, rs1);
                    atomicAdd(dst + 2, rs2); atomicAdd(dst + 3, rs3);
                }
                cur = b; rs0 = o0; rs1 = o1; rs2 = o2; rs3 = o3;
            } else { rs0 += o0; rs1 += o1; rs2 += o2; rs3 += o3; }
        }
    }
    if (cur >= 0) {
        float* dst = spill ? &g_seg1[cur*64 + cg*4] : &segbuf[cur - sb0][cg*4];
        atomicAdd(dst + 0, rs0); atomicAdd(dst + 1, rs1);
        atomicAdd(dst + 2, rs2); atomicAdd(dst + 3, rs3);
    }
    __syncthreads();
    if (!spill) {
        for (int idx = tid; idx < nseg * 64; idx += 256) {
            int s = idx >> 6, c = idx & 63;
            float v = segbuf[s][c];
            if (v != 0.f) atomicAdd(&g_seg1[(sb0 + s)*64 + c], v);
        }
    }
}

// ---------------- KP1: xm1 = (seg1/cnt) @ l1w  (2000x64 @ 64x64) ---------------
__global__ __launch_bounds__(256) void kp1(const float* __restrict__ lw) {
    __shared__ float Ls[64 * 64];
    __shared__ float mean[4][64];
    int tid = threadIdx.x;
    for (int i = tid; i < 4096; i += 256) Ls[i] = lw[i];
    int g0 = blockIdx.x * 16;
    int gl = tid >> 6, j = tid & 63;
    for (int t = 0; t < 4; t++) {
        int b = g0 + t*4 + gl;
        __syncthreads();
        mean[gl][j] = g_seg1[b*64 + j] * g_inv[b];
        __syncthreads();
        float s = 0.f;
#pragma unroll
        for (int k = 0; k < 64; k++) s += mean[gl][k] * Ls[k*64 + j];
        g_xm1[b*64 + j] = s;
    }
}

// ---------------- K3: h1 = relu(x0 @ g1_w + g1_b - xm1[batch]); fused seg-sum --
// BM=128, K=64 single-stage, 256 threads, tile 8 rows x 4 cols.
__global__ __launch_bounds__(256) void k3_h1(
    const float* __restrict__ gw, const float* __restrict__ gb,
    const int* __restrict__ batch, int N)
{
    __shared__ __align__(16) float As[64][132];     // 132*4 % 16 == 0
    __shared__ __align__(16) float Ws[64 * 64];
    __shared__ __align__(16) float segbuf[16][64];
    __shared__ int sb[128];
    int tid = threadIdx.x;
    int n0  = blockIdx.x * 128;

    for (int i = tid; i < 64 * 64; i += 256) Ws[i] = gw[i];
    for (int i = tid; i < 16 * 64; i += 256) ((float*)segbuf)[i] = 0.f;
    if (tid < 128) { int r = n0 + tid; sb[tid] = (r < N) ? batch[r] : batch[N - 1]; }

    {
        int k4 = tid & 15;
#pragma unroll
        for (int p = 0; p < 8; p++) {
            int lr  = (tid >> 4) + 16 * p;
            int row = n0 + lr;
            float4 v = (row < N)
                ? *(const float4*)&g_x0[(size_t)row*64 + k4*4]
                : make_float4(0.f, 0.f, 0.f, 0.f);
            As[k4*4 + 0][lr] = v.x;
            As[k4*4 + 1][lr] = v.y;
            As[k4*4 + 2][lr] = v.z;
            As[k4*4 + 3][lr] = v.w;
        }
    }
    __syncthreads();

    int rg = tid >> 4, cg = tid & 15;
    ull acc[8][2];
#pragma unroll
    for (int r = 0; r < 8; r++) { acc[r][0] = 0ull; acc[r][1] = 0ull; }

    const ull* Wsu = (const ull*)Ws;
#pragma unroll 8
    for (int k = 0; k < 64; k++) {
        float4 a0 = *(const float4*)&As[k][rg*8];
        float4 a1 = *(const float4*)&As[k][rg*8 + 4];
        ull w0 = Wsu[k*32 + cg*2];
        ull w1 = Wsu[k*32 + cg*2 + 1];
        float av[8] = {a0.x, a0.y, a0.z, a0.w, a1.x, a1.y, a1.z, a1.w};
#pragma unroll
        for (int r = 0; r < 8; r++) {
            ull ar = pack2(av[r]);
            ffma2(acc[r][0], ar, w0);
            ffma2(acc[r][1], ar, w1);
        }
    }

    int sb0 = sb[0];
    int nseg = sb[127] - sb0 + 1;
    bool spill = nseg > 16;

    float4 bias = *(const float4*)&gb[cg*4];
    int cur = -1;
    float rs0 = 0.f, rs1 = 0.f, rs2 = 0.f, rs3 = 0.f;
#pragma unroll
    for (int r = 0; r < 8; r++) {
        int lr  = rg*8 + r;
        int row = n0 + lr;
        if (row < N) {
            int b = sb[lr];
            float4 xl = *(const float4*)&g_xm1[b*64 + cg*4];
            float2 p0 = unpk(acc[r][0]), p1 = unpk(acc[r][1]);
            float o0 = fmaxf(p0.x + bias.x - xl.x, 0.f);
            float o1 = fmaxf(p0.y + bias.y - xl.y, 0.f);
            float o2 = fmaxf(p1.x + bias.z - xl.z, 0.f);
            float o3 = fmaxf(p1.y + bias.w - xl.w, 0.f);
            *(float4*)&g_h1[(size_t)row*64 + cg*4] = make_float4(o0, o1, o2, o3);
            if (b != cur) {
                if (cur >= 0) {
                    float* dst = spill ? &g_seg2[cur*64 + cg*4] : &segbuf[cur - sb0][cg*4];
                    atomicAdd(dst + 0, rs0); atomicAdd(dst + 1, rs1);
                    atomicAdd(dst + 2, rs2); atomicAdd(dst + 3, rs3);
                }
                cur = b; rs0 = o0; rs1 = o1; rs2 = o2; rs3 = o3;
            } else { rs0 += o0; rs1 += o1; rs2 += o2; rs3 += o3; }
        }
    }
    if (cur >= 0) {
        float* dst = spill ? &g_seg2[cur*64 + cg*4] : &segbuf[cur - sb0][cg*4];
        atomicAdd(dst + 0, rs0); atomicAdd(dst + 1, rs1);
        atomicAdd(dst + 2, rs2); atomicAdd(dst + 3, rs3);
    }
    __syncthreads();
    if (!spill) {
        for (int idx = tid; idx < nseg * 64; idx += 256) {
            int s = idx >> 6, c = idx & 63;
            float v = segbuf[s][c];
            if (v != 0.f) atomicAdd(&g_seg2[(sb0 + s)*64 + c], v);
        }
    }
}

// ---------------- KP2: xm2 = (seg2/cnt) @ l2w  (2000x64 @ 64x128) --------------
__global__ __launch_bounds__(256) void kp2(const float* __restrict__ lw) {
    __shared__ float Ls[64 * 128];
    __shared__ float mean[2][64];
    int tid = threadIdx.x;
    for (int i = tid; i < 8192; i += 256) Ls[i] = lw[i];
    int g0 = blockIdx.x * 16;
    int gl = tid >> 7, j = tid & 127;
    for (int t = 0; t < 8; t++) {
        __syncthreads();
        if (tid < 128) {
            int bb = g0 + t*2 + (tid >> 6);
            mean[tid >> 6][tid & 63] = g_seg2[bb*64 + (tid & 63)] * g_inv[bb];
        }
        __syncthreads();
        int b = g0 + t*2 + gl;
        float s = 0.f;
#pragma unroll
        for (int k = 0; k < 64; k++) s += mean[gl][k] * Ls[k*128 + j];
        g_xm2[b*128 + j] = s;
    }
}

// ---------------- K5: v = relu(h1 @ g2_w + g2_b - xm2[batch]); BN stats --------
// BM=64, BN=128, K=64 single-stage, 256 threads, tile 4 rows x 8 cols (split).
__global__ __launch_bounds__(256) void k5_v(
    const float* __restrict__ gw, const float* __restrict__ gb,
    const int* __restrict__ batch, int N)
{
    __shared__ __align__(16) float As[64][68];      // 68*4 % 16 == 0
    __shared__ __align__(16) float Ws[64 * 128];
    __shared__ int sb[64];
    int tid = threadIdx.x;
    int n0  = blockIdx.x * 64;

    for (int i = tid; i < 64 * 128; i += 256) Ws[i] = gw[i];
    if (tid < 64) { int r = n0 + tid; sb[tid] = (r < N) ? batch[r] : batch[N - 1]; }

    {
        int k4 = tid & 15;
#pragma unroll
        for (int p = 0; p < 4; p++) {
            int lr  = (tid >> 4) + 16 * p;
            int row = n0 + lr;
            float4 v = (row < N)
                ? *(const float4*)&g_h1[(size_t)row*64 + k4*4]
                : make_float4(0.f, 0.f, 0.f, 0.f);
            As[k4*4 + 0][lr] = v.x;
            As[k4*4 + 1][lr] = v.y;
            As[k4*4 + 2][lr] = v.z;
            As[k4*4 + 3][lr] = v.w;
        }
    }
    __syncthreads();

    int rg = tid >> 4, cg = tid & 15;
    ull acc[4][4];
#pragma unroll
    for (int r = 0; r < 4; r++)
#pragma unroll
        for (int c = 0; c < 4; c++) acc[r][c] = 0ull;

    const ull* Wsu = (const ull*)Ws;
#pragma unroll 8
    for (int k = 0; k < 64; k++) {
        float4 a = *(const float4*)&As[k][rg*4];
        ull w0 = Wsu[k*64 + cg*2];
        ull w1 = Wsu[k*64 + cg*2 + 1];
        ull w2 = Wsu[k*64 + 32 + cg*2];
        ull w3 = Wsu[k*64 + 32 + cg*2 + 1];
        float av[4] = {a.x, a.y, a.z, a.w};
#pragma unroll
        for (int r = 0; r < 4; r++) {
            ull ar = pack2(av[r]);
            ffma2(acc[r][0], ar, w0);
            ffma2(acc[r][1], ar, w1);
            ffma2(acc[r][2], ar, w2);
            ffma2(acc[r][3], ar, w3);
        }
    }

    float4 bl = *(const float4*)&gb[cg*4];
    float4 bh = *(const float4*)&gb[64 + cg*4];
    float cs[8], cq[8];
#pragma unroll
    for (int i = 0; i < 8; i++) { cs[i] = 0.f; cq[i] = 0.f; }

#pragma unroll
    for (int r = 0; r < 4; r++) {
        int lr  = rg*4 + r;
        int row = n0 + lr;
        if (row < N) {
            int b = sb[lr];
            float4 xl = *(const float4*)&g_xm2[b*128 + cg*4];
            float4 xh = *(const float4*)&g_xm2[b*128 + 64 + cg*4];
            float2 p0 = unpk(acc[r][0]), p1 = unpk(acc[r][1]);
            float2 p2 = unpk(acc[r][2]), p3 = unpk(acc[r][3]);
            float o[8];
            o[0] = fmaxf(p0.x + bl.x - xl.x, 0.f);
            o[1] = fmaxf(p0.y + bl.y - xl.y, 0.f);
            o[2] = fmaxf(p1.x + bl.z - xl.z, 0.f);
            o[3] = fmaxf(p1.y + bl.w - xl.w, 0.f);
            o[4] = fmaxf(p2.x + bh.x - xh.x, 0.f);
            o[5] = fmaxf(p2.y + bh.y - xh.y, 0.f);
            o[6] = fmaxf(p3.x + bh.z - xh.z, 0.f);
            o[7] = fmaxf(p3.y + bh.w - xh.w, 0.f);
            __half2 p01 = __floats2half2_rn(o[0], o[1]);
            __half2 p23 = __floats2half2_rn(o[2], o[3]);
            __half2 p45 = __floats2half2_rn(o[4], o[5]);
            __half2 p67 = __floats2half2_rn(o[6], o[7]);
            uint2 lo2, hi2;
            lo2.x = *reinterpret_cast<unsigned*>(&p01);
            lo2.y = *reinterpret_cast<unsigned*>(&p23);
            hi2.x = *reinterpret_cast<unsigned*>(&p45);
            hi2.y = *reinterpret_cast<unsigned*>(&p67);
            *reinterpret_cast<uint2*>(&g_vh[(size_t)row*128 + cg*4])      = lo2;
            *reinterpret_cast<uint2*>(&g_vh[(size_t)row*128 + 64 + cg*4]) = hi2;
#pragma unroll
            for (int i = 0; i < 8; i++) { cs[i] += o[i]; cq[i] += o[i] * o[i]; }
        }
    }

    // stats reduction: shfl rg-pair within warp, smem over 8 warps, atomics
#pragma unroll
    for (int i = 0; i < 8; i++) {
        cs[i] += __shfl_xor_sync(0xffffffffu, cs[i], 16);
        cq[i] += __shfl_xor_sync(0xffffffffu, cq[i], 16);
    }
    __syncthreads();                 // all warps done reading As
    float* red = &As[0][0];          // [8 warps][16 cg][16]
    int lane = tid & 31, w = tid >> 5;
    if (lane < 16) {
#pragma unroll
        for (int i = 0; i < 8; i++) {
            red[w*256 + lane*16 + i]     = cs[i];
            red[w*256 + lane*16 + 8 + i] = cq[i];
        }
    }
    __syncthreads();
    if (tid < 128) {
        int c   = tid;
        int cg2 = (c & 63) >> 2;
        int ii  = (c < 64) ? (c & 3) : 4 + (c & 3);
        float s = 0.f, q = 0.f;
#pragma unroll
        for (int w2 = 0; w2 < 8; w2++) {
            s += red[w2*256 + cg2*16 + ii];
            q += red[w2*256 + cg2*16 + 8 + ii];
        }
        atomicAdd(&g_fsum[c], s);
        atomicAdd(&g_fsq[c],  q);
    }
}

// ---------------- K5b: fold BN into scale/shift --------------------------------
__global__ void k5b_stats(const float* __restrict__ gamma,
                          const float* __restrict__ beta, float invN)
{
    int t = threadIdx.x;
    if (t < 128) {
        float m   = g_fsum[t] * invN;
        float var = g_fsq[t] * invN - m * m;
        float rs  = rsqrtf(var + 1e-5f);
        float sc  = gamma[t] * rs;
        g_scale[t] = sc;
        g_shift[t] = beta[t] - m * sc;
    }
}

// ---------------- K6: out = x + v*scale + shift ---------------------------------
__global__ __launch_bounds__(256) void k6_out(const float* __restrict__ x,
                                              float* __restrict__ out, int n4)
{
    int i = blockIdx.x * 256 + threadIdx.x;
    if (i < n4) {
        float4 xv = ((const float4*)x)[i];
        uint2 hv  = ((const uint2*)g_vh)[i];
        __half2 ha = *reinterpret_cast<__half2*>(&hv.x);
        __half2 hb = *reinterpret_cast<__half2*>(&hv.y);
        float2 f01 = __half22float2(ha);
        float2 f23 = __half22float2(hb);
        int f = i & 31;
        float4 sc = ((const float4*)g_scale)[f];
        float4 sh = ((const float4*)g_shift)[f];
        float4 o;
        o.x = fmaf(f01.x, sc.x, xv.x + sh.x);
        o.y = fmaf(f01.y, sc.y, xv.y + sh.y);
        o.z = fmaf(f23.x, sc.z, xv.z + sh.z);
        o.w = fmaf(f23.y, sc.w, xv.w + sh.w);
        ((float4*)out)[i] = o;
    }
}

// ---------------- launch --------------------------------------------------------
extern "C" void kernel_launch(void* const* d_in, const int* in_sizes, int n_in,
                              void* d_out, int out_size)
{
    const float* x    = (const float*)d_in[0];
    const float* pp   = (const float*)d_in[1];
    const int*   batch= (const int*)  d_in[2];
    const float* W0   = (const float*)d_in[3];
    const float* b0   = (const float*)d_in[4];
    const float* g1w  = (const float*)d_in[5];
    const float* g1b  = (const float*)d_in[6];
    const float* l1w  = (const float*)d_in[7];
    const float* g2w  = (const float*)d_in[8];
    const float* g2b  = (const float*)d_in[9];
    const float* l2w  = (const float*)d_in[10];
    const float* bng  = (const float*)d_in[11];
    const float* bnb  = (const float*)d_in[12];
    float* out = (float*)d_out;

    int N = in_sizes[2];
    int nb128 = (N + 127) / 128;
    int nb64  = (N + 63) / 64;
    int n4    = N * 32;

    k0_zero<<<(2 * BG * 64 + 128 + 255) / 256, 256>>>();
    kc_inv <<<(BG + 255) / 256, 256>>>(batch, N);
    k1_x0  <<<nb128, 256>>>(pp, W0, b0, batch, N);
    kp1    <<<BG / 16, 256>>>(l1w);
    k3_h1  <<<nb128, 256>>>(g1w, g1b, batch, N);
    kp2    <<<BG / 16, 256>>>(l2w);
    k5_v   <<<nb64, 256>>>(g2w, g2b, batch, N);
    k5b_stats<<<1, 128>>>(bng, bnb, 1.0f / (float)N);
    k6_out <<<(n4 + 255) / 256, 256>>>(x, out, n4);
}

// round 9
// speedup vs baseline: 1.8660x; 1.7117x over previous
#include <cuda_runtime.h>
#include <cuda_fp16.h>
#include <cstdint>

typedef unsigned long long ull;

#define NMAX 1000000
#define BG   2000
#define NPAD 128

// ---------------- scratch (device globals: allocation-free rule) --------------
__device__ __align__(16) __half g_x0h[((size_t)NMAX + NPAD) * 64];
__device__ __align__(16) __half g_h1h[((size_t)NMAX + NPAD) * 64];
__device__ __align__(16) __half g_vh [((size_t)NMAX + NPAD) * 128];
__device__ __align__(16) __half g_w1t[64 * 64];     // g1_w transposed [n][k] fp16
__device__ __align__(16) __half g_w2t[128 * 64];    // g2_w transposed [n][k] fp16
__device__ __align__(16) float  g_seg1[BG * 64];
__device__ __align__(16) float  g_seg2[BG * 64];
__device__ __align__(16) float  g_xm1[BG * 64];
__device__ __align__(16) float  g_xm2[BG * 128];
__device__ float g_inv[BG];
__device__ float g_fsum[128];
__device__ float g_fsq [128];
__device__ __align__(16) float g_scale[128];
__device__ __align__(16) float g_shift[128];

// ---------------- f32x2 helpers (K1 scalar path) -------------------------------
__device__ __forceinline__ void ffma2(ull &acc, ull a, ull b) {
    asm("fma.rn.f32x2 %0, %1, %2, %0;" : "+l"(acc) : "l"(a), "l"(b));
}
__device__ __forceinline__ ull pack2(float x) {
    ull r; unsigned u = __float_as_uint(x);
    asm("mov.b64 %0, {%1, %1};" : "=l"(r) : "r"(u));
    return r;
}
__device__ __forceinline__ float2 unpk(ull v) {
    unsigned lo, hi;
    asm("mov.b64 {%0, %1}, %2;" : "=r"(lo), "=r"(hi) : "l"(v));
    return make_float2(__uint_as_float(lo), __uint_as_float(hi));
}

__device__ __forceinline__ int lbound(const int* __restrict__ a, int n, int v) {
    int lo = 0, hi = n;
    while (lo < hi) { int m = (lo + hi) >> 1; if (__ldg(a + m) < v) lo = m + 1; else hi = m; }
    return lo;
}

// ---------------- warp MMA helpers (plain PTX, no 'a' features) -----------------
__device__ __forceinline__ uint32_t smem_u32(const void* p) {
    uint32_t a;
    asm("{ .reg .u64 t; cvta.to.shared.u64 t, %1; cvt.u32.u64 %0, t; }" : "=r"(a) : "l"(p));
    return a;
}
__device__ __forceinline__ void ldsm_x4(uint32_t &r0, uint32_t &r1, uint32_t &r2, uint32_t &r3,
                                        uint32_t addr) {
    asm volatile("ldmatrix.sync.aligned.m8n8.x4.shared.b16 {%0,%1,%2,%3}, [%4];"
                 : "=r"(r0), "=r"(r1), "=r"(r2), "=r"(r3) : "r"(addr));
}
__device__ __forceinline__ void ldsm_x2(uint32_t &r0, uint32_t &r1, uint32_t addr) {
    asm volatile("ldmatrix.sync.aligned.m8n8.x2.shared.b16 {%0,%1}, [%2];"
                 : "=r"(r0), "=r"(r1) : "r"(addr));
}
__device__ __forceinline__ void mma16816(float* c, uint32_t a0, uint32_t a1, uint32_t a2,
                                         uint32_t a3, uint32_t b0, uint32_t b1) {
    asm volatile("mma.sync.aligned.m16n8k16.row.col.f32.f16.f16.f32 "
                 "{%0,%1,%2,%3}, {%4,%5,%6,%7}, {%8,%9}, {%0,%1,%2,%3};"
                 : "+f"(c[0]), "+f"(c[1]), "+f"(c[2]), "+f"(c[3])
                 : "r"(a0), "r"(a1), "r"(a2), "r"(a3), "r"(b0), "r"(b1));
}

// ---------------- K0: zero accumulators ----------------------------------------
__global__ void k0_zero() {
    int i = blockIdx.x * 256 + threadIdx.x;
    if (i < BG * 64) g_seg1[i] = 0.f;
    int j = i - BG * 64;
    if (j >= 0 && j < BG * 64) g_seg2[j] = 0.f;
    int k = i - 2 * BG * 64;
    if (k >= 0 && k < 128) { g_fsum[k] = 0.f; g_fsq[k] = 0.f; }
}

// ---------------- KC: inverse counts --------------------------------------------
__global__ void kc_inv(const int* __restrict__ batch, int N) {
    int b = blockIdx.x * 256 + threadIdx.x;
    if (b < BG) {
        int lo = lbound(batch, N, b), hi = lbound(batch, N, b + 1);
        int c = hi - lo;
        g_inv[b] = 1.f / (float)(c > 0 ? c : 1);
    }
}

// ---------------- KW: transpose weights to fp16 ---------------------------------
__global__ void kw_prep(const float* __restrict__ g1w, const float* __restrict__ g2w) {
    int i = blockIdx.x * 256 + threadIdx.x;
    if (i < 64 * 64) {
        int n = i >> 6, k = i & 63;
        g_w1t[i] = __float2half_rn(g1w[k * 64 + n]);
    }
    int j = i - 64 * 64;
    if (j >= 0 && j < 128 * 64) {
        int n = j >> 6, k = j & 63;
        g_w2t[j] = __float2half_rn(g2w[k * 128 + n]);
    }
}

// ---------------- K1: x0 = relu(pack(pp) @ W0 + b0) -> fp16; fused seg-sum ------
__global__ __launch_bounds__(256) void k1_x0(
    const float* __restrict__ pp, const float* __restrict__ W0,
    const float* __restrict__ b0, const int* __restrict__ batch, int N)
{
    __shared__ __align__(16) float As[16][132];
    __shared__ __align__(16) float Ws[16 * 64];
    __shared__ __align__(16) float segbuf[16][64];
    __shared__ int sb[128];
    int tid = threadIdx.x;
    int n0  = blockIdx.x * 128;

    for (int i = tid; i < 16 * 64; i += 256) Ws[i] = W0[i];
    for (int i = tid; i < 16 * 64; i += 256) ((float*)segbuf)[i] = 0.f;
    if (tid < 128) { int r = n0 + tid; sb[tid] = (r < N) ? batch[r] : batch[N - 1]; }

    const float2* pp2 = (const float2*)pp;
    {
        int n  = tid & 127;
        int fb = tid >> 7;
        int gn = n0 + n;
#pragma unroll
        for (int p = 0; p < 4; p++) {
            int f = fb + 2 * p;
            float2 v = (gn < N) ? pp2[(size_t)f * N + gn] : make_float2(0.f, 0.f);
            As[2*f    ][n] = v.x;
            As[2*f + 1][n] = v.y;
        }
    }
    __syncthreads();

    int rg = tid >> 4, cg = tid & 15;
    ull acc[8][2];
#pragma unroll
    for (int r = 0; r < 8; r++) { acc[r][0] = 0ull; acc[r][1] = 0ull; }

    const ull* Wsu = (const ull*)Ws;
#pragma unroll
    for (int k = 0; k < 16; k++) {
        float4 a0 = *(const float4*)&As[k][rg*8];
        float4 a1 = *(const float4*)&As[k][rg*8 + 4];
        ull w0 = Wsu[k*32 + cg*2];
        ull w1 = Wsu[k*32 + cg*2 + 1];
        float av[8] = {a0.x, a0.y, a0.z, a0.w, a1.x, a1.y, a1.z, a1.w};
#pragma unroll
        for (int r = 0; r < 8; r++) {
            ull ar = pack2(av[r]);
            ffma2(acc[r][0], ar, w0);
            ffma2(acc[r][1], ar, w1);
        }
    }

    int sb0 = sb[0];
    int nseg = sb[127] - sb0 + 1;
    bool spill = nseg > 16;

    float4 bias = *(const float4*)&b0[cg*4];
    int cur = -1;
    float rs0 = 0.f, rs1 = 0.f, rs2 = 0.f, rs3 = 0.f;
#pragma unroll
    for (int r = 0; r < 8; r++) {
        int lr  = rg*8 + r;
        int row = n0 + lr;
        if (row < N) {
            float2 p0 = unpk(acc[r][0]), p1 = unpk(acc[r][1]);
            float o0 = fmaxf(p0.x + bias.x, 0.f);
            float o1 = fmaxf(p0.y + bias.y, 0.f);
            float o2 = fmaxf(p1.x + bias.z, 0.f);
            float o3 = fmaxf(p1.y + bias.w, 0.f);
            __half2 h01 = __floats2half2_rn(o0, o1);
            __half2 h23 = __floats2half2_rn(o2, o3);
            uint2 u;
            u.x = *reinterpret_cast<unsigned*>(&h01);
            u.y = *reinterpret_cast<unsigned*>(&h23);
            *reinterpret_cast<uint2*>(&g_x0h[(size_t)row*64 + cg*4]) = u;
            int b = sb[lr];
            if (b != cur) {
                if (cur >= 0) {
                    float* dst = spill ? &g_seg1[cur*64 + cg*4] : &segbuf[cur - sb0][cg*4];
                    atomicAdd(dst + 0, rs0); atomicAdd(dst + 1, rs1);
                    atomicAdd(dst + 2, rs2); atomicAdd(dst + 3, rs3);
                }
                cur = b; rs0 = o0; rs1 = o1; rs2 = o2; rs3 = o3;
            } else { rs0 += o0; rs1 += o1; rs2 += o2; rs3 += o3; }
        }
    }
    if (cur >= 0) {
        float* dst = spill ? &g_seg1[cur*64 + cg*4] : &segbuf[cur - sb0][cg*4];
        atomicAdd(dst + 0, rs0); atomicAdd(dst + 1, rs1);
        atomicAdd(dst + 2, rs2); atomicAdd(dst + 3, rs3);
    }
    __syncthreads();
    if (!spill) {
        for (int idx = tid; idx < nseg * 64; idx += 256) {
            int s = idx >> 6, c = idx & 63;
            float v = segbuf[s][c];
            if (v != 0.f) atomicAdd(&g_seg1[(sb0 + s)*64 + c], v);
        }
    }
}

// ---------------- KP1 / KP2: xm = (seg/cnt) @ lw ---------------------------------
__global__ __launch_bounds__(256) void kp1(const float* __restrict__ lw) {
    __shared__ float Ls[64 * 64];
    __shared__ float mean[4][64];
    int tid = threadIdx.x;
    for (int i = tid; i < 4096; i += 256) Ls[i] = lw[i];
    int g0 = blockIdx.x * 16;
    int gl = tid >> 6, j = tid & 63;
    for (int t = 0; t < 4; t++) {
        int b = g0 + t*4 + gl;
        __syncthreads();
        mean[gl][j] = g_seg1[b*64 + j] * g_inv[b];
        __syncthreads();
        float s = 0.f;
#pragma unroll
        for (int k = 0; k < 64; k++) s += mean[gl][k] * Ls[k*64 + j];
        g_xm1[b*64 + j] = s;
    }
}

__global__ __launch_bounds__(256) void kp2(const float* __restrict__ lw) {
    __shared__ float Ls[64 * 128];
    __shared__ float mean[2][64];
    int tid = threadIdx.x;
    for (int i = tid; i < 8192; i += 256) Ls[i] = lw[i];
    int g0 = blockIdx.x * 16;
    int gl = tid >> 7, j = tid & 127;
    for (int t = 0; t < 8; t++) {
        __syncthreads();
        if (tid < 128) {
            int bb = g0 + t*2 + (tid >> 6);
            mean[tid >> 6][tid & 63] = g_seg2[bb*64 + (tid & 63)] * g_inv[bb];
        }
        __syncthreads();
        int b = g0 + t*2 + gl;
        float s = 0.f;
#pragma unroll
        for (int k = 0; k < 64; k++) s += mean[gl][k] * Ls[k*128 + j];
        g_xm2[b*128 + j] = s;
    }
}

// ---------------- K3: mma.sync h1 = relu(x0 @ g1w + b - xm1); fused seg-sum -----
// 128 rows/block, 256 threads (8 warps, 4x2 warp grid).
__global__ __launch_bounds__(256) void k3_h1(
    const float* __restrict__ gb, const int* __restrict__ batch, int N)
{
    __shared__ __align__(16) __half Ah[128][72];      // A tile; reused as output stage
    __shared__ __align__(16) __half Wh[64][72];       // W1^T [n][k]
    __shared__ __align__(16) float  xoffS[16][64];
    __shared__ __align__(16) float  segbuf[16][64];
    __shared__ int sb[128];
    int tid = threadIdx.x;
    int n0  = blockIdx.x * 128;

    if (tid < 128) { int r = n0 + tid; sb[tid] = (r < N) ? batch[r] : batch[N - 1]; }

    const uint4* srcA = (const uint4*)(g_x0h + (size_t)n0 * 64);
#pragma unroll
    for (int i = tid; i < 1024; i += 256) {
        int r = i >> 3, c = (i & 7) * 8;
        *(uint4*)&Ah[r][c] = srcA[i];
    }
    const uint4* srcB = (const uint4*)g_w1t;
#pragma unroll
    for (int i = tid; i < 512; i += 256) {
        int r = i >> 3, c = (i & 7) * 8;
        *(uint4*)&Wh[r][c] = srcB[i];
    }
    __syncthreads();

    int sb0 = sb[0];
    int nseg = sb[127] - sb0 + 1;
    int ns = nseg < 16 ? nseg : 16;
    for (int i = tid; i < ns * 64; i += 256) {
        int s = i >> 6, c = i & 63;
        xoffS[s][c] = gb[c] - g_xm1[(size_t)(sb0 + s) * 64 + c];
    }
    for (int i = tid; i < 16 * 64; i += 256) ((float*)segbuf)[i] = 0.f;
    __syncthreads();

    int w = tid >> 5, lane = tid & 31;
    int wm = w & 3, wn = w >> 2;          // 4 x 2 warp grid
    int m0 = wm * 32, nb = wn * 32;

    float acc[2][4][4];
#pragma unroll
    for (int mt = 0; mt < 2; mt++)
#pragma unroll
        for (int nt = 0; nt < 4; nt++)
#pragma unroll
            for (int i = 0; i < 4; i++) acc[mt][nt][i] = 0.f;

    uint32_t aAddr[2], bAddr[4];
#pragma unroll
    for (int mt = 0; mt < 2; mt++)
        aAddr[mt] = smem_u32(&Ah[m0 + 16*mt + (lane & 15)][8 * (lane >> 4)]);
#pragma unroll
    for (int nt = 0; nt < 4; nt++)
        bAddr[nt] = smem_u32(&Wh[nb + 8*nt + (lane & 7)][8 * ((lane >> 3) & 1)]);

#pragma unroll
    for (int ks = 0; ks < 4; ks++) {
        uint32_t a[2][4];
#pragma unroll
        for (int mt = 0; mt < 2; mt++)
            ldsm_x4(a[mt][0], a[mt][1], a[mt][2], a[mt][3], aAddr[mt] + ks * 32);
#pragma unroll
        for (int nt = 0; nt < 4; nt++) {
            uint32_t b0, b1;
            ldsm_x2(b0, b1, bAddr[nt] + ks * 32);
#pragma unroll
            for (int mt = 0; mt < 2; mt++)
                mma16816(acc[mt][nt], a[mt][0], a[mt][1], a[mt][2], a[mt][3], b0, b1);
        }
    }
    __syncthreads();            // done reading Ah/Wh; reuse Ah as output stage

    __half (*oS)[72] = Ah;
#pragma unroll
    for (int mt = 0; mt < 2; mt++) {
#pragma unroll
        for (int pr = 0; pr < 2; pr++) {
            int lr = m0 + 16*mt + 8*pr + (lane >> 2);
            int si = sb[lr] - sb0;
            size_t bb = (size_t)sb[lr] * 64;
#pragma unroll
            for (int nt = 0; nt < 4; nt++) {
                int col = nb + 8*nt + 2*(lane & 3);
                float2 off;
                if (si < 16) off = *(const float2*)&xoffS[si][col];
                else off = make_float2(gb[col] - g_xm1[bb + col],
                                       gb[col+1] - g_xm1[bb + col + 1]);
                float v0 = fmaxf(acc[mt][nt][pr*2 + 0] + off.x, 0.f);
                float v1 = fmaxf(acc[mt][nt][pr*2 + 1] + off.y, 0.f);
                *(__half2*)&oS[lr][col] = __floats2half2_rn(v0, v1);
            }
        }
    }
    __syncthreads();

    // coalesced oS -> g_h1h
    {
        __half* dst = g_h1h + (size_t)n0 * 64;
#pragma unroll
        for (int i = tid; i < 1024; i += 256) {
            int r = i >> 3, c = (i & 7) * 8;
            *(uint4*)(dst + (size_t)r * 64 + c) = *(const uint4*)&oS[r][c];
        }
    }

    // seg-sums from staged tile (run-accumulation, 16 rg x 16 cg of 4 cols)
    {
        int rg = tid >> 4, cg = tid & 15;
        int cur = -1;
        float rs0 = 0.f, rs1 = 0.f, rs2 = 0.f, rs3 = 0.f;
#pragma unroll
        for (int r = 0; r < 8; r++) {
            int lr = rg * 8 + r;
            if (n0 + lr >= N) break;
            uint2 u = *(const uint2*)&oS[lr][cg * 4];
            __half2 ha = *reinterpret_cast<__half2*>(&u.x);
            __half2 hb = *reinterpret_cast<__half2*>(&u.y);
            float2 f0 = __half22float2(ha), f1 = __half22float2(hb);
            int b = sb[lr];
            if (b != cur) {
                if (cur >= 0) {
                    int si = cur - sb0;
                    float* dst = (si < 16) ? &segbuf[si][cg * 4]
                                           : &g_seg2[(size_t)cur * 64 + cg * 4];
                    atomicAdd(dst + 0, rs0); atomicAdd(dst + 1, rs1);
                    atomicAdd(dst + 2, rs2); atomicAdd(dst + 3, rs3);
                }
                cur = b; rs0 = f0.x; rs1 = f0.y; rs2 = f1.x; rs3 = f1.y;
            } else { rs0 += f0.x; rs1 += f0.y; rs2 += f1.x; rs3 += f1.y; }
        }
        if (cur >= 0) {
            int si = cur - sb0;
            float* dst = (si < 16) ? &segbuf[si][cg * 4]
                                   : &g_seg2[(size_t)cur * 64 + cg * 4];
            atomicAdd(dst + 0, rs0); atomicAdd(dst + 1, rs1);
            atomicAdd(dst + 2, rs2); atomicAdd(dst + 3, rs3);
        }
    }
    __syncthreads();
    for (int i = tid; i < ns * 64; i += 256) {
        float v = ((const float*)segbuf)[i];
        if (v != 0.f) atomicAdd(&g_seg2[(size_t)(sb0 + (i >> 6)) * 64 + (i & 63)], v);
    }
}

// ---------------- K5: mma.sync v = relu(h1 @ g2w + b - xm2); BN stats -----------
// 128 rows/block, 256 threads (8 warps, 4x2 warp grid, N=128).
__global__ __launch_bounds__(256) void k5_v(
    const float* __restrict__ gb, const int* __restrict__ batch, int N)
{
    __shared__ __align__(16) __half AW[128*72 + 128*72];  // A | W; reused as oS [128][136]
    __shared__ __align__(16) float  xoffS[16][128];       // reused as stats buf
    __shared__ int sb[128];
    int tid = threadIdx.x;
    int n0  = blockIdx.x * 128;

    __half (*Ah)[72] = (__half(*)[72])AW;
    __half (*Wh)[72] = (__half(*)[72])(AW + 128*72);

    if (tid < 128) { int r = n0 + tid; sb[tid] = (r < N) ? batch[r] : batch[N - 1]; }

    const uint4* srcA = (const uint4*)(g_h1h + (size_t)n0 * 64);
#pragma unroll
    for (int i = tid; i < 1024; i += 256) {
        int r = i >> 3, c = (i & 7) * 8;
        *(uint4*)&Ah[r][c] = srcA[i];
    }
    const uint4* srcB = (const uint4*)g_w2t;
#pragma unroll
    for (int i = tid; i < 1024; i += 256) {
        int r = i >> 3, c = (i & 7) * 8;
        *(uint4*)&Wh[r][c] = srcB[i];
    }
    __syncthreads();

    int sb0 = sb[0];
    int nseg = sb[127] - sb0 + 1;
    int ns = nseg < 16 ? nseg : 16;
    for (int i = tid; i < ns * 128; i += 256) {
        int s = i >> 7, c = i & 127;
        xoffS[s][c] = gb[c] - g_xm2[(size_t)(sb0 + s) * 128 + c];
    }
    __syncthreads();

    int w = tid >> 5, lane = tid & 31;
    int wm = w & 3, wn = w >> 2;
    int m0 = wm * 32, nb = wn * 64;

    float acc[2][8][4];
#pragma unroll
    for (int mt = 0; mt < 2; mt++)
#pragma unroll
        for (int nt = 0; nt < 8; nt++)
#pragma unroll
            for (int i = 0; i < 4; i++) acc[mt][nt][i] = 0.f;

    uint32_t aAddr[2], bAddr[8];
#pragma unroll
    for (int mt = 0; mt < 2; mt++)
        aAddr[mt] = smem_u32(&Ah[m0 + 16*mt + (lane & 15)][8 * (lane >> 4)]);
#pragma unroll
    for (int nt = 0; nt < 8; nt++)
        bAddr[nt] = smem_u32(&Wh[nb + 8*nt + (lane & 7)][8 * ((lane >> 3) & 1)]);

#pragma unroll
    for (int ks = 0; ks < 4; ks++) {
        uint32_t a[2][4];
#pragma unroll
        for (int mt = 0; mt < 2; mt++)
            ldsm_x4(a[mt][0], a[mt][1], a[mt][2], a[mt][3], aAddr[mt] + ks * 32);
#pragma unroll
        for (int nt = 0; nt < 8; nt++) {
            uint32_t b0, b1;
            ldsm_x2(b0, b1, bAddr[nt] + ks * 32);
#pragma unroll
            for (int mt = 0; mt < 2; mt++)
                mma16816(acc[mt][nt], a[mt][0], a[mt][1], a[mt][2], a[mt][3], b0, b1);
        }
    }
    __syncthreads();            // done reading Ah/Wh; reuse AW as oS [128][136]

    __half (*oS)[136] = (__half(*)[136])AW;
#pragma unroll
    for (int mt = 0; mt < 2; mt++) {
#pragma unroll
        for (int pr = 0; pr < 2; pr++) {
            int lr = m0 + 16*mt + 8*pr + (lane >> 2);
            int si = sb[lr] - sb0;
            size_t bb = (size_t)sb[lr] * 128;
#pragma unroll
            for (int nt = 0; nt < 8; nt++) {
                int col = nb + 8*nt + 2*(lane & 3);
                float2 off;
                if (si < 16) off = *(const float2*)&xoffS[si][col];
                else off = make_float2(gb[col] - g_xm2[bb + col],
                                       gb[col+1] - g_xm2[bb + col + 1]);
                float v0 = fmaxf(acc[mt][nt][pr*2 + 0] + off.x, 0.f);
                float v1 = fmaxf(acc[mt][nt][pr*2 + 1] + off.y, 0.f);
                *(__half2*)&oS[lr][col] = __floats2half2_rn(v0, v1);
            }
        }
    }
    __syncthreads();

    // coalesced oS -> g_vh
    {
        __half* dst = g_vh + (size_t)n0 * 128;
#pragma unroll
        for (int i = tid; i < 2048; i += 256) {
            int r = i >> 4, c = (i & 15) * 8;
            *(uint4*)(dst + (size_t)r * 128 + c) = *(const uint4*)&oS[r][c];
        }
    }

    // BN stats: 16 rg x 16 cg of 8 cols; shfl16 then smem over 8 warps
    {
        int rg = tid >> 4, cg = tid & 15;
        float cs[8], cq[8];
#pragma unroll
        for (int i = 0; i < 8; i++) { cs[i] = 0.f; cq[i] = 0.f; }
#pragma unroll
        for (int r = 0; r < 8; r++) {
            int lr = rg * 8 + r;
            if (n0 + lr >= N) break;
            uint4 u = *(const uint4*)&oS[lr][cg * 8];
            const __half2* hp = (const __half2*)&u;
#pragma unroll
            for (int q = 0; q < 4; q++) {
                float2 f = __half22float2(hp[q]);
                cs[q*2 + 0] += f.x; cq[q*2 + 0] += f.x * f.x;
                cs[q*2 + 1] += f.y; cq[q*2 + 1] += f.y * f.y;
            }
        }
#pragma unroll
        for (int i = 0; i < 8; i++) {
            cs[i] += __shfl_xor_sync(0xffffffffu, cs[i], 16);
            cq[i] += __shfl_xor_sync(0xffffffffu, cq[i], 16);
        }
        __syncthreads();        // done reading oS; reuse xoffS as stats buf
        float* csA = &xoffS[0][0];       // [8 warps][128]
        float* cqA = csA + 1024;         // [8 warps][128]
        if (lane < 16) {
#pragma unroll
            for (int i = 0; i < 8; i++) {
                csA[w * 128 + lane * 8 + i] = cs[i];
                cqA[w * 128 + lane * 8 + i] = cq[i];
            }
        }
        __syncthreads();
        if (tid < 128) {
            float s = 0.f, q = 0.f;
#pragma unroll
            for (int ww = 0; ww < 8; ww++) {
                s += csA[ww * 128 + tid];
                q += cqA[ww * 128 + tid];
            }
            atomicAdd(&g_fsum[tid], s);
            atomicAdd(&g_fsq [tid], q);
        }
    }
}

// ---------------- K5b: fold BN into scale/shift ---------------------------------
__global__ void k5b_stats(const float* __restrict__ gamma,
                          const float* __restrict__ beta, float invN)
{
    int t = threadIdx.x;
    if (t < 128) {
        float m   = g_fsum[t] * invN;
        float var = g_fsq[t] * invN - m * m;
        float rs  = rsqrtf(var + 1e-5f);
        float sc  = gamma[t] * rs;
        g_scale[t] = sc;
        g_shift[t] = beta[t] - m * sc;
    }
}

// ---------------- K6: out = x + v*scale + shift ----------------------------------
__global__ __launch_bounds__(256) void k6_out(const float* __restrict__ x,
                                              float* __restrict__ out, int n4)
{
    int i = blockIdx.x * 256 + threadIdx.x;
    if (i < n4) {
        float4 xv = ((const float4*)x)[i];
        uint2 hv  = ((const uint2*)g_vh)[i];
        __half2 ha = *reinterpret_cast<__half2*>(&hv.x);
        __half2 hb = *reinterpret_cast<__half2*>(&hv.y);
        float2 f01 = __half22float2(ha);
        float2 f23 = __half22float2(hb);
        int f = i & 31;
        float4 sc = ((const float4*)g_scale)[f];
        float4 sh = ((const float4*)g_shift)[f];
        float4 o;
        o.x = fmaf(f01.x, sc.x, xv.x + sh.x);
        o.y = fmaf(f01.y, sc.y, xv.y + sh.y);
        o.z = fmaf(f23.x, sc.z, xv.z + sh.z);
        o.w = fmaf(f23.y, sc.w, xv.w + sh.w);
        ((float4*)out)[i] = o;
    }
}

// ---------------- launch ----------------------------------------------------------
extern "C" void kernel_launch(void* const* d_in, const int* in_sizes, int n_in,
                              void* d_out, int out_size)
{
    const float* x    = (const float*)d_in[0];
    const float* pp   = (const float*)d_in[1];
    const int*   batch= (const int*)  d_in[2];
    const float* W0   = (const float*)d_in[3];
    const float* b0   = (const float*)d_in[4];
    const float* g1w  = (const float*)d_in[5];
    const float* g1b  = (const float*)d_in[6];
    const float* l1w  = (const float*)d_in[7];
    const float* g2w  = (const float*)d_in[8];
    const float* g2b  = (const float*)d_in[9];
    const float* l2w  = (const float*)d_in[10];
    const float* bng  = (const float*)d_in[11];
    const float* bnb  = (const float*)d_in[12];
    float* out = (float*)d_out;

    int N = in_sizes[2];
    int nb128 = (N + 127) / 128;
    int n4    = N * 32;

    k0_zero<<<(2 * BG * 64 + 128 + 255) / 256, 256>>>();
    kc_inv <<<(BG + 255) / 256, 256>>>(batch, N);
    kw_prep<<<(64*64 + 128*64 + 255) / 256, 256>>>(g1w, g2w);
    k1_x0  <<<nb128, 256>>>(pp, W0, b0, batch, N);
    kp1    <<<BG / 16, 256>>>(l1w);
    k3_h1  <<<nb128, 256>>>(g1b, batch, N);
    kp2    <<<BG / 16, 256>>>(l2w);
    k5_v   <<<nb128, 256>>>(g2b, batch, N);
    k5b_stats<<<1, 128>>>(bng, bnb, 1.0f / (float)N);
    k6_out <<<(n4 + 255) / 256, 256>>>(x, out, n4);
}

// round 12
// speedup vs baseline: 1.8926x; 1.0143x over previous
#include <cuda_runtime.h>
#include <cuda_fp16.h>
#include <cstdint>

typedef unsigned long long ull;

#define NMAX 1000000
#define BG   2000
#define NPAD 128

// ---------------- scratch (device globals: allocation-free rule) --------------
__device__ __align__(16) __half g_x0h[((size_t)NMAX + NPAD) * 64];
__device__ __align__(16) __half g_h1h[((size_t)NMAX + NPAD) * 64];
__device__ __align__(16) __half g_vh [((size_t)NMAX + NPAD) * 128];
__device__ __align__(16) __half g_w1t[64 * 64];     // g1_w transposed [n][k] fp16
__device__ __align__(16) __half g_w2t[128 * 64];    // g2_w transposed [n][k] fp16
__device__ __align__(16) float  g_seg1[BG * 64];
__device__ __align__(16) float  g_seg2[BG * 64];
__device__ __align__(16) float  g_xm1[BG * 64];
__device__ __align__(16) float  g_xm2[BG * 128];
__device__ float g_inv[BG];
__device__ float g_fsum[128];
__device__ float g_fsq [128];
__device__ __align__(16) float g_scale[128];
__device__ __align__(16) float g_shift[128];

// ---------------- f32x2 helpers (K1 scalar path) -------------------------------
__device__ __forceinline__ void ffma2(ull &acc, ull a, ull b) {
    asm("fma.rn.f32x2 %0, %1, %2, %0;" : "+l"(acc) : "l"(a), "l"(b));
}
__device__ __forceinline__ ull pack2(float x) {
    ull r; unsigned u = __float_as_uint(x);
    asm("mov.b64 %0, {%1, %1};" : "=l"(r) : "r"(u));
    return r;
}
__device__ __forceinline__ float2 unpk(ull v) {
    unsigned lo, hi;
    asm("mov.b64 {%0, %1}, %2;" : "=r"(lo), "=r"(hi) : "l"(v));
    return make_float2(__uint_as_float(lo), __uint_as_float(hi));
}

__device__ __forceinline__ int lbound(const int* __restrict__ a, int n, int v) {
    int lo = 0, hi = n;
    while (lo < hi) { int m = (lo + hi) >> 1; if (__ldg(a + m) < v) lo = m + 1; else hi = m; }
    return lo;
}

// ---------------- warp MMA helpers (plain PTX, no 'a' features) -----------------
__device__ __forceinline__ uint32_t smem_u32(const void* p) {
    uint32_t a;
    asm("{ .reg .u64 t; cvta.to.shared.u64 t, %1; cvt.u32.u64 %0, t; }" : "=r"(a) : "l"(p));
    return a;
}
__device__ __forceinline__ void ldsm_x4(uint32_t &r0, uint32_t &r1, uint32_t &r2, uint32_t &r3,
                                        uint32_t addr) {
    asm volatile("ldmatrix.sync.aligned.m8n8.x4.shared.b16 {%0,%1,%2,%3}, [%4];"
                 : "=r"(r0), "=r"(r1), "=r"(r2), "=r"(r3) : "r"(addr));
}
__device__ __forceinline__ void ldsm_x2(uint32_t &r0, uint32_t &r1, uint32_t addr) {
    asm volatile("ldmatrix.sync.aligned.m8n8.x2.shared.b16 {%0,%1}, [%2];"
                 : "=r"(r0), "=r"(r1) : "r"(addr));
}
__device__ __forceinline__ void mma16816(float* c, uint32_t a0, uint32_t a1, uint32_t a2,
                                         uint32_t a3, uint32_t b0, uint32_t b1) {
    asm volatile("mma.sync.aligned.m16n8k16.row.col.f32.f16.f16.f32 "
                 "{%0,%1,%2,%3}, {%4,%5,%6,%7}, {%8,%9}, {%0,%1,%2,%3};"
                 : "+f"(c[0]), "+f"(c[1]), "+f"(c[2]), "+f"(c[3])
                 : "r"(a0), "r"(a1), "r"(a2), "r"(a3), "r"(b0), "r"(b1));
}

// ---------------- K_PREP: zero accumulators + inv counts + weight transpose -----
__global__ void k_prep(const int* __restrict__ batch,
                       const float* __restrict__ g1w, const float* __restrict__ g2w, int N) {
    int i = blockIdx.x * 256 + threadIdx.x;
    if (i < BG * 64) { g_seg1[i] = 0.f; g_seg2[i] = 0.f; }
    if (i < 128)     { g_fsum[i] = 0.f; g_fsq[i] = 0.f; }
    if (i < BG) {
        int lo = lbound(batch, N, i), hi = lbound(batch, N, i + 1);
        int c = hi - lo;
        g_inv[i] = 1.f / (float)(c > 0 ? c : 1);
    }
    if (i < 64 * 64) {
        int n = i >> 6, k = i & 63;
        g_w1t[i] = __float2half_rn(g1w[k * 64 + n]);
    }
    if (i < 128 * 64) {
        int n = i >> 6, k = i & 63;
        g_w2t[i] = __float2half_rn(g2w[k * 128 + n]);
    }
}

// ---------------- K1: x0 = relu(pack(pp) @ W0 + b0) -> fp16; fused seg-sum ------
__global__ __launch_bounds__(256) void k1_x0(
    const float* __restrict__ pp, const float* __restrict__ W0,
    const float* __restrict__ b0, const int* __restrict__ batch, int N)
{
    __shared__ __align__(16) float As[16][132];
    __shared__ __align__(16) float Ws[16 * 64];
    __shared__ __align__(16) float segbuf[16][64];
    __shared__ int sb[128];
    int tid = threadIdx.x;
    int n0  = blockIdx.x * 128;

    for (int i = tid; i < 16 * 64; i += 256) Ws[i] = W0[i];
    for (int i = tid; i < 16 * 64; i += 256) ((float*)segbuf)[i] = 0.f;
    if (tid < 128) { int r = n0 + tid; sb[tid] = (r < N) ? batch[r] : batch[N - 1]; }

    const float2* pp2 = (const float2*)pp;
    {
        int n  = tid & 127;
        int fb = tid >> 7;
        int gn = n0 + n;
#pragma unroll
        for (int p = 0; p < 4; p++) {
            int f = fb + 2 * p;
            float2 v = (gn < N) ? pp2[(size_t)f * N + gn] : make_float2(0.f, 0.f);
            As[2*f    ][n] = v.x;
            As[2*f + 1][n] = v.y;
        }
    }
    __syncthreads();

    int rg = tid >> 4, cg = tid & 15;
    ull acc[8][2];
#pragma unroll
    for (int r = 0; r < 8; r++) { acc[r][0] = 0ull; acc[r][1] = 0ull; }

    const ull* Wsu = (const ull*)Ws;
#pragma unroll
    for (int k = 0; k < 16; k++) {
        float4 a0 = *(const float4*)&As[k][rg*8];
        float4 a1 = *(const float4*)&As[k][rg*8 + 4];
        ull w0 = Wsu[k*32 + cg*2];
        ull w1 = Wsu[k*32 + cg*2 + 1];
        float av[8] = {a0.x, a0.y, a0.z, a0.w, a1.x, a1.y, a1.z, a1.w};
#pragma unroll
        for (int r = 0; r < 8; r++) {
            ull ar = pack2(av[r]);
            ffma2(acc[r][0], ar, w0);
            ffma2(acc[r][1], ar, w1);
        }
    }

    int sb0 = sb[0];
    int nseg = sb[127] - sb0 + 1;
    bool spill = nseg > 16;

    float4 bias = *(const float4*)&b0[cg*4];
    int cur = -1;
    float rs0 = 0.f, rs1 = 0.f, rs2 = 0.f, rs3 = 0.f;
#pragma unroll
    for (int r = 0; r < 8; r++) {
        int lr  = rg*8 + r;
        int row = n0 + lr;
        if (row < N) {
            float2 p0 = unpk(acc[r][0]), p1 = unpk(acc[r][1]);
            float o0 = fmaxf(p0.x + bias.x, 0.f);
            float o1 = fmaxf(p0.y + bias.y, 0.f);
            float o2 = fmaxf(p1.x + bias.z, 0.f);
            float o3 = fmaxf(p1.y + bias.w, 0.f);
            __half2 h01 = __floats2half2_rn(o0, o1);
            __half2 h23 = __floats2half2_rn(o2, o3);
            uint2 u;
            u.x = *reinterpret_cast<unsigned*>(&h01);
            u.y = *reinterpret_cast<unsigned*>(&h23);
            *reinterpret_cast<uint2*>(&g_x0h[(size_t)row*64 + cg*4]) = u;
            int b = sb[lr];
            if (b != cur) {
                if (cur >= 0) {
                    float* dst = spill ? &g_seg1[cur*64 + cg*4] : &segbuf[cur - sb0][cg*4];
                    atomicAdd(dst + 0, rs0); atomicAdd(dst + 1, rs1);
                    atomicAdd(dst + 2, rs2); atomicAdd(dst + 3, rs3);
                }
                cur = b; rs0 = o0; rs1 = o1; rs2 = o2; rs3 = o3;
            } else { rs0 += o0; rs1 += o1; rs2 += o2; rs3 += o3; }
        }
    }
    if (cur >= 0) {
        float* dst = spill ? &g_seg1[cur*64 + cg*4] : &segbuf[cur - sb0][cg*4];
        atomicAdd(dst + 0, rs0); atomicAdd(dst + 1, rs1);
        atomicAdd(dst + 2, rs2); atomicAdd(dst + 3, rs3);
    }
    __syncthreads();
    if (!spill) {
        for (int idx = tid; idx < nseg * 64; idx += 256) {
            int s = idx >> 6, c = idx & 63;
            float v = segbuf[s][c];
            if (v != 0.f) atomicAdd(&g_seg1[(sb0 + s)*64 + c], v);
        }
    }
}

// ---------------- KP1: 8 graphs/block (250 blocks), 2-step loop ------------------
__global__ __launch_bounds__(256) void kp1(const float* __restrict__ lw) {
    __shared__ float Ls[64 * 64];
    __shared__ float mean[4][64];
    int tid = threadIdx.x;
    for (int i = tid; i < 4096; i += 256) Ls[i] = lw[i];
    int g0 = blockIdx.x * 8;
    int gl = tid >> 6, j = tid & 63;
#pragma unroll
    for (int t = 0; t < 2; t++) {
        int b = g0 + t*4 + gl;
        __syncthreads();
        mean[gl][j] = g_seg1[b*64 + j] * g_inv[b];
        __syncthreads();
        float s = 0.f;
#pragma unroll
        for (int k = 0; k < 64; k++) s += mean[gl][k] * Ls[k*64 + j];
        g_xm1[b*64 + j] = s;
    }
}

// ---------------- KP2: 4 graphs/block (500 blocks), 2-step loop ------------------
__global__ __launch_bounds__(256) void kp2(const float* __restrict__ lw) {
    __shared__ float Ls[64 * 128];
    __shared__ float mean[2][64];
    int tid = threadIdx.x;
    for (int i = tid; i < 8192; i += 256) Ls[i] = lw[i];
    int g0 = blockIdx.x * 4;
    int gl = tid >> 7, j = tid & 127;
#pragma unroll
    for (int t = 0; t < 2; t++) {
        __syncthreads();
        if (tid < 128) {
            int bb = g0 + t*2 + (tid >> 6);
            mean[tid >> 6][tid & 63] = g_seg2[bb*64 + (tid & 63)] * g_inv[bb];
        }
        __syncthreads();
        int b = g0 + t*2 + gl;
        float s = 0.f;
#pragma unroll
        for (int k = 0; k < 64; k++) s += mean[gl][k] * Ls[k*128 + j];
        g_xm2[b*128 + j] = s;
    }
}

// ---------------- K3: mma.sync h1 = relu(x0 @ g1w + b - xm1); fused seg-sum -----
// 128 rows/block, 256 threads (8 warps, 4x2 warp grid).
__global__ __launch_bounds__(256) void k3_h1(
    const float* __restrict__ gb, const int* __restrict__ batch, int N)
{
    __shared__ __align__(16) __half Ah[128][72];      // A tile; reused as output stage
    __shared__ __align__(16) __half Wh[64][72];       // W1^T [n][k]
    __shared__ __align__(16) float  xoffS[16][64];
    __shared__ __align__(16) float  segbuf[16][64];
    __shared__ int sb[128];
    int tid = threadIdx.x;
    int n0  = blockIdx.x * 128;

    if (tid < 128) { int r = n0 + tid; sb[tid] = (r < N) ? batch[r] : batch[N - 1]; }

    const uint4* srcA = (const uint4*)(g_x0h + (size_t)n0 * 64);
#pragma unroll
    for (int i = tid; i < 1024; i += 256) {
        int r = i >> 3, c = (i & 7) * 8;
        *(uint4*)&Ah[r][c] = srcA[i];
    }
    const uint4* srcB = (const uint4*)g_w1t;
#pragma unroll
    for (int i = tid; i < 512; i += 256) {
        int r = i >> 3, c = (i & 7) * 8;
        *(uint4*)&Wh[r][c] = srcB[i];
    }
    __syncthreads();

    int sb0 = sb[0];
    int nseg = sb[127] - sb0 + 1;
    int ns = nseg < 16 ? nseg : 16;
    for (int i = tid; i < ns * 64; i += 256) {
        int s = i >> 6, c = i & 63;
        xoffS[s][c] = gb[c] - g_xm1[(size_t)(sb0 + s) * 64 + c];
    }
    for (int i = tid; i < 16 * 64; i += 256) ((float*)segbuf)[i] = 0.f;
    __syncthreads();

    int w = tid >> 5, lane = tid & 31;
    int wm = w & 3, wn = w >> 2;          // 4 x 2 warp grid
    int m0 = wm * 32, nb = wn * 32;

    float acc[2][4][4];
#pragma unroll
    for (int mt = 0; mt < 2; mt++)
#pragma unroll
        for (int nt = 0; nt < 4; nt++)
#pragma unroll
            for (int i = 0; i < 4; i++) acc[mt][nt][i] = 0.f;

    uint32_t aAddr[2], bAddr[4];
#pragma unroll
    for (int mt = 0; mt < 2; mt++)
        aAddr[mt] = smem_u32(&Ah[m0 + 16*mt + (lane & 15)][8 * (lane >> 4)]);
#pragma unroll
    for (int nt = 0; nt < 4; nt++)
        bAddr[nt] = smem_u32(&Wh[nb + 8*nt + (lane & 7)][8 * ((lane >> 3) & 1)]);

#pragma unroll
    for (int ks = 0; ks < 4; ks++) {
        uint32_t a[2][4];
#pragma unroll
        for (int mt = 0; mt < 2; mt++)
            ldsm_x4(a[mt][0], a[mt][1], a[mt][2], a[mt][3], aAddr[mt] + ks * 32);
#pragma unroll
        for (int nt = 0; nt < 4; nt++) {
            uint32_t b0, b1;
            ldsm_x2(b0, b1, bAddr[nt] + ks * 32);
#pragma unroll
            for (int mt = 0; mt < 2; mt++)
                mma16816(acc[mt][nt], a[mt][0], a[mt][1], a[mt][2], a[mt][3], b0, b1);
        }
    }
    __syncthreads();            // done reading Ah/Wh; reuse Ah as output stage

    __half (*oS)[72] = Ah;
#pragma unroll
    for (int mt = 0; mt < 2; mt++) {
#pragma unroll
        for (int pr = 0; pr < 2; pr++) {
            int lr = m0 + 16*mt + 8*pr + (lane >> 2);
            int si = sb[lr] - sb0;
            size_t bb = (size_t)sb[lr] * 64;
#pragma unroll
            for (int nt = 0; nt < 4; nt++) {
                int col = nb + 8*nt + 2*(lane & 3);
                float2 off;
                if (si < 16) off = *(const float2*)&xoffS[si][col];
                else off = make_float2(gb[col] - g_xm1[bb + col],
                                       gb[col+1] - g_xm1[bb + col + 1]);
                float v0 = fmaxf(acc[mt][nt][pr*2 + 0] + off.x, 0.f);
                float v1 = fmaxf(acc[mt][nt][pr*2 + 1] + off.y, 0.f);
                *(__half2*)&oS[lr][col] = __floats2half2_rn(v0, v1);
            }
        }
    }
    __syncthreads();

    // coalesced oS -> g_h1h
    {
        __half* dst = g_h1h + (size_t)n0 * 64;
#pragma unroll
        for (int i = tid; i < 1024; i += 256) {
            int r = i >> 3, c = (i & 7) * 8;
            *(uint4*)(dst + (size_t)r * 64 + c) = *(const uint4*)&oS[r][c];
        }
    }

    // seg-sums from staged tile (run-accumulation, 16 rg x 16 cg of 4 cols)
    {
        int rg = tid >> 4, cg = tid & 15;
        int cur = -1;
        float rs0 = 0.f, rs1 = 0.f, rs2 = 0.f, rs3 = 0.f;
#pragma unroll
        for (int r = 0; r < 8; r++) {
            int lr = rg * 8 + r;
            if (n0 + lr >= N) break;
            uint2 u = *(const uint2*)&oS[lr][cg * 4];
            __half2 ha = *reinterpret_cast<__half2*>(&u.x);
            __half2 hb = *reinterpret_cast<__half2*>(&u.y);
            float2 f0 = __half22float2(ha), f1 = __half22float2(hb);
            int b = sb[lr];
            if (b != cur) {
                if (cur >= 0) {
                    int si = cur - sb0;
                    float* dst = (si < 16) ? &segbuf[si][cg * 4]
                                           : &g_seg2[(size_t)cur * 64 + cg * 4];
                    atomicAdd(dst + 0, rs0); atomicAdd(dst + 1, rs1);
                    atomicAdd(dst + 2, rs2); atomicAdd(dst + 3, rs3);
                }
                cur = b; rs0 = f0.x; rs1 = f0.y; rs2 = f1.x; rs3 = f1.y;
            } else { rs0 += f0.x; rs1 += f0.y; rs2 += f1.x; rs3 += f1.y; }
        }
        if (cur >= 0) {
            int si = cur - sb0;
            float* dst = (si < 16) ? &segbuf[si][cg * 4]
                                   : &g_seg2[(size_t)cur * 64 + cg * 4];
            atomicAdd(dst + 0, rs0); atomicAdd(dst + 1, rs1);
            atomicAdd(dst + 2, rs2); atomicAdd(dst + 3, rs3);
        }
    }
    __syncthreads();
    for (int i = tid; i < ns * 64; i += 256) {
        float v = ((const float*)segbuf)[i];
        if (v != 0.f) atomicAdd(&g_seg2[(size_t)(sb0 + (i >> 6)) * 64 + (i & 63)], v);
    }
}

// ---------------- K5: mma.sync v = relu(h1 @ g2w + b - xm2); BN stats -----------
// 128 rows/block, 256 threads (8 warps, 4x2 warp grid, N=128).
__global__ __launch_bounds__(256) void k5_v(
    const float* __restrict__ gb, const int* __restrict__ batch, int N)
{
    __shared__ __align__(16) __half AW[128*72 + 128*72];  // A | W; reused as oS [128][136]
    __shared__ __align__(16) float  xoffS[16][128];       // reused as stats buf
    __shared__ int sb[128];
    int tid = threadIdx.x;
    int n0  = blockIdx.x * 128;

    __half (*Ah)[72] = (__half(*)[72])AW;
    __half (*Wh)[72] = (__half(*)[72])(AW + 128*72);

    if (tid < 128) { int r = n0 + tid; sb[tid] = (r < N) ? batch[r] : batch[N - 1]; }

    const uint4* srcA = (const uint4*)(g_h1h + (size_t)n0 * 64);
#pragma unroll
    for (int i = tid; i < 1024; i += 256) {
        int r = i >> 3, c = (i & 7) * 8;
        *(uint4*)&Ah[r][c] = srcA[i];
    }
    const uint4* srcB = (const uint4*)g_w2t;
#pragma unroll
    for (int i = tid; i < 1024; i += 256) {
        int r = i >> 3, c = (i & 7) * 8;
        *(uint4*)&Wh[r][c] = srcB[i];
    }
    __syncthreads();

    int sb0 = sb[0];
    int nseg = sb[127] - sb0 + 1;
    int ns = nseg < 16 ? nseg : 16;
    for (int i = tid; i < ns * 128; i += 256) {
        int s = i >> 7, c = i & 127;
        xoffS[s][c] = gb[c] - g_xm2[(size_t)(sb0 + s) * 128 + c];
    }
    __syncthreads();

    int w = tid >> 5, lane = tid & 31;
    int wm = w & 3, wn = w >> 2;
    int m0 = wm * 32, nb = wn * 64;

    float acc[2][8][4];
#pragma unroll
    for (int mt = 0; mt < 2; mt++)
#pragma unroll
        for (int nt = 0; nt < 8; nt++)
#pragma unroll
            for (int i = 0; i < 4; i++) acc[mt][nt][i] = 0.f;

    uint32_t aAddr[2], bAddr[8];
#pragma unroll
    for (int mt = 0; mt < 2; mt++)
        aAddr[mt] = smem_u32(&Ah[m0 + 16*mt + (lane & 15)][8 * (lane >> 4)]);
#pragma unroll
    for (int nt = 0; nt < 8; nt++)
        bAddr[nt] = smem_u32(&Wh[nb + 8*nt + (lane & 7)][8 * ((lane >> 3) & 1)]);

#pragma unroll
    for (int ks = 0; ks < 4; ks++) {
        uint32_t a[2][4];
#pragma unroll
        for (int mt = 0; mt < 2; mt++)
            ldsm_x4(a[mt][0], a[mt][1], a[mt][2], a[mt][3], aAddr[mt] + ks * 32);
#pragma unroll
        for (int nt = 0; nt < 8; nt++) {
            uint32_t b0, b1;
            ldsm_x2(b0, b1, bAddr[nt] + ks * 32);
#pragma unroll
            for (int mt = 0; mt < 2; mt++)
                mma16816(acc[mt][nt], a[mt][0], a[mt][1], a[mt][2], a[mt][3], b0, b1);
        }
    }
    __syncthreads();            // done reading Ah/Wh; reuse AW as oS [128][136]

    __half (*oS)[136] = (__half(*)[136])AW;
#pragma unroll
    for (int mt = 0; mt < 2; mt++) {
#pragma unroll
        for (int pr = 0; pr < 2; pr++) {
            int lr = m0 + 16*mt + 8*pr + (lane >> 2);
            int si = sb[lr] - sb0;
            size_t bb = (size_t)sb[lr] * 128;
#pragma unroll
            for (int nt = 0; nt < 8; nt++) {
                int col = nb + 8*nt + 2*(lane & 3);
                float2 off;
                if (si < 16) off = *(const float2*)&xoffS[si][col];
                else off = make_float2(gb[col] - g_xm2[bb + col],
                                       gb[col+1] - g_xm2[bb + col + 1]);
                float v0 = fmaxf(acc[mt][nt][pr*2 + 0] + off.x, 0.f);
                float v1 = fmaxf(acc[mt][nt][pr*2 + 1] + off.y, 0.f);
                *(__half2*)&oS[lr][col] = __floats2half2_rn(v0, v1);
            }
        }
    }
    __syncthreads();

    // coalesced oS -> g_vh
    {
        __half* dst = g_vh + (size_t)n0 * 128;
#pragma unroll
        for (int i = tid; i < 2048; i += 256) {
            int r = i >> 4, c = (i & 15) * 8;
            *(uint4*)(dst + (size_t)r * 128 + c) = *(const uint4*)&oS[r][c];
        }
    }

    // BN stats: 16 rg x 16 cg of 8 cols; shfl16 then smem over 8 warps
    {
        int rg = tid >> 4, cg = tid & 15;
        float cs[8], cq[8];
#pragma unroll
        for (int i = 0; i < 8; i++) { cs[i] = 0.f; cq[i] = 0.f; }
#pragma unroll
        for (int r = 0; r < 8; r++) {
            int lr = rg * 8 + r;
            if (n0 + lr >= N) break;
            uint4 u = *(const uint4*)&oS[lr][cg * 8];
            const __half2* hp = (const __half2*)&u;
#pragma unroll
            for (int q = 0; q < 4; q++) {
                float2 f = __half22float2(hp[q]);
                cs[q*2 + 0] += f.x; cq[q*2 + 0] += f.x * f.x;
                cs[q*2 + 1] += f.y; cq[q*2 + 1] += f.y * f.y;
            }
        }
#pragma unroll
        for (int i = 0; i < 8; i++) {
            cs[i] += __shfl_xor_sync(0xffffffffu, cs[i], 16);
            cq[i] += __shfl_xor_sync(0xffffffffu, cq[i], 16);
        }
        __syncthreads();        // done reading oS; reuse xoffS as stats buf
        float* csA = &xoffS[0][0];       // [8 warps][128]
        float* cqA = csA + 1024;         // [8 warps][128]
        if (lane < 16) {
#pragma unroll
            for (int i = 0; i < 8; i++) {
                csA[w * 128 + lane * 8 + i] = cs[i];
                cqA[w * 128 + lane * 8 + i] = cq[i];
            }
        }
        __syncthreads();
        if (tid < 128) {
            float s = 0.f, q = 0.f;
#pragma unroll
            for (int ww = 0; ww < 8; ww++) {
                s += csA[ww * 128 + tid];
                q += cqA[ww * 128 + tid];
            }
            atomicAdd(&g_fsum[tid], s);
            atomicAdd(&g_fsq [tid], q);
        }
    }
}

// ---------------- K5b: fold BN into scale/shift ---------------------------------
__global__ void k5b_stats(const float* __restrict__ gamma,
                          const float* __restrict__ beta, float invN)
{
    int t = threadIdx.x;
    if (t < 128) {
        float m   = g_fsum[t] * invN;
        float var = g_fsq[t] * invN - m * m;
        float rs  = rsqrtf(var + 1e-5f);
        float sc  = gamma[t] * rs;
        g_scale[t] = sc;
        g_shift[t] = beta[t] - m * sc;
    }
}

// ---------------- K6: out = x + v*scale + shift (8 floats/thread, streaming) -----
__global__ __launch_bounds__(256) void k6_out(const float* __restrict__ x,
                                              float* __restrict__ out, int nv)
{
    __shared__ __align__(16) float scS[128];
    __shared__ __align__(16) float shS[128];
    int tid = threadIdx.x;
    if (tid < 128) { scS[tid] = g_scale[tid]; shS[tid] = g_shift[tid]; }
    __syncthreads();

    int i = blockIdx.x * 256 + tid;
    if (i < nv) {
        uint4  hv = __ldcs((const uint4*)g_vh + i);
        float4 x0 = __ldcs((const float4*)x + 2*i);
        float4 x1 = __ldcs((const float4*)x + 2*i + 1);
        int f = (i & 15) * 8;
        float4 sc0 = *(const float4*)&scS[f];
        float4 sc1 = *(const float4*)&scS[f + 4];
        float4 sh0 = *(const float4*)&shS[f];
        float4 sh1 = *(const float4*)&shS[f + 4];
        const __half2* hp = (const __half2*)&hv;
        float2 f0 = __half22float2(hp[0]);
        float2 f1 = __half22float2(hp[1]);
        float2 f2 = __half22float2(hp[2]);
        float2 f3 = __half22float2(hp[3]);
        float4 o0, o1;
        o0.x = fmaf(f0.x, sc0.x, x0.x + sh0.x);
        o0.y = fmaf(f0.y, sc0.y, x0.y + sh0.y);
        o0.z = fmaf(f1.x, sc0.z, x0.z + sh0.z);
        o0.w = fmaf(f1.y, sc0.w, x0.w + sh0.w);
        o1.x = fmaf(f2.x, sc1.x, x1.x + sh1.x);
        o1.y = fmaf(f2.y, sc1.y, x1.y + sh1.y);
        o1.z = fmaf(f3.x, sc1.z, x1.z + sh1.z);
        o1.w = fmaf(f3.y, sc1.w, x1.w + sh1.w);
        __stcs((float4*)out + 2*i,     o0);
        __stcs((float4*)out + 2*i + 1, o1);
    }
}

// ---------------- launch ----------------------------------------------------------
extern "C" void kernel_launch(void* const* d_in, const int* in_sizes, int n_in,
                              void* d_out, int out_size)
{
    const float* x    = (const float*)d_in[0];
    const float* pp   = (const float*)d_in[1];
    const int*   batch= (const int*)  d_in[2];
    const float* W0   = (const float*)d_in[3];
    const float* b0   = (const float*)d_in[4];
    const float* g1w  = (const float*)d_in[5];
    const float* g1b  = (const float*)d_in[6];
    const float* l1w  = (const float*)d_in[7];
    const float* g2w  = (const float*)d_in[8];
    const float* g2b  = (const float*)d_in[9];
    const float* l2w  = (const float*)d_in[10];
    const float* bng  = (const float*)d_in[11];
    const float* bnb  = (const float*)d_in[12];
    float* out = (float*)d_out;

    int N = in_sizes[2];
    int nb128 = (N + 127) / 128;
    int nv    = N * 16;                        // 8 floats per thread

    k_prep <<<(BG * 64 + 255) / 256, 256>>>(batch, g1w, g2w, N);
    k1_x0  <<<nb128, 256>>>(pp, W0, b0, batch, N);
    kp1    <<<BG / 8, 256>>>(l1w);
    k3_h1  <<<nb128, 256>>>(g1b, batch, N);
    kp2    <<<BG / 4, 256>>>(l2w);
    k5_v   <<<nb128, 256>>>(g2b, batch, N);
    k5b_stats<<<1, 128>>>(bng, bnb, 1.0f / (float)N);
    k6_out <<<(nv + 255) / 256, 256>>>(x, out, nv);
}